// round 5
// baseline (speedup 1.0000x reference)
#include <cuda_runtime.h>

// Problem constants
#define Bb   8
#define Cc   256
#define Nn   2048
#define Kk   16
#define OUTd 256
#define KD   512                 // 2*C
#define BN_TOT (Bb*Nn)           // 16384

// ---- scratch (static device globals; no dynamic allocation) ----
__device__ float g_xsT [BN_TOT * Cc];   // [B*N, C] node-major features
__device__ float g_si  [BN_TOT];
__device__ float g_sj  [BN_TOT];
__device__ float g_w   [BN_TOT * Kk];   // softmax weights
__device__ int   g_j   [BN_TOT * Kk];   // neighbor indices (int32)
__device__ float g_feat[BN_TOT * KD];   // [B*N, 2C] interleaved (xs, agg)
__device__ int   g_is64;                // 1 if edge buffer is int64 viewed as int32 pairs

// ============================================================
// K0: detect edge dtype. Valid indices are < 2048, so if the
// buffer is int64, every odd int32 word is 0 (little-endian).
// ============================================================
__global__ void k_detect(const int* __restrict__ e) {
    const int t = threadIdx.x;
    int bad = 0;
    #pragma unroll
    for (int i = t; i < 256; i += 32) bad |= e[2 * i + 1];
    #pragma unroll
    for (int o = 16; o; o >>= 1) bad |= __shfl_xor_sync(0xffffffffu, bad, o);
    if (!t) g_is64 = (bad == 0) ? 1 : 0;
}

// ============================================================
// K1: transpose xs [B,C,N] -> xsT [B*N, C]
// ============================================================
__global__ void k_transpose(const float* __restrict__ x) {
    __shared__ float tile[32][33];
    const int b  = blockIdx.z;
    const int n0 = blockIdx.x * 32;
    const int c0 = blockIdx.y * 32;
    const float* xb = x + (size_t)b * Cc * Nn;
    #pragma unroll
    for (int i = 0; i < 32; i += 8)
        tile[threadIdx.y + i][threadIdx.x] =
            xb[(size_t)(c0 + threadIdx.y + i) * Nn + n0 + threadIdx.x];
    __syncthreads();
    float* xt = g_xsT + (size_t)b * Nn * Cc;
    #pragma unroll
    for (int i = 0; i < 32; i += 8)
        xt[(size_t)(n0 + threadIdx.y + i) * Cc + c0 + threadIdx.x] =
            tile[threadIdx.x][threadIdx.y + i];
}

// ============================================================
// K2: per-node attention pre-scores s_i, s_j (one warp per node)
// ============================================================
__global__ void k_scores(const float* __restrict__ aw) {
    const int gw   = (blockIdx.x * blockDim.x + threadIdx.x) >> 5;
    const int lane = threadIdx.x & 31;
    if (gw >= BN_TOT) return;
    const float4* v  = (const float4*)(g_xsT + (size_t)gw * Cc);
    const float4* wi = (const float4*)aw;
    const float4* wj = (const float4*)(aw + Cc);
    float ai = 0.f, aj = 0.f;
    #pragma unroll
    for (int r = 0; r < 2; r++) {
        const int idx = lane + r * 32;
        float4 xv = v[idx], w1 = wi[idx], w2 = wj[idx];
        ai += xv.x * w1.x + xv.y * w1.y + xv.z * w1.z + xv.w * w1.w;
        aj += xv.x * w2.x + xv.y * w2.y + xv.z * w2.z + xv.w * w2.w;
    }
    #pragma unroll
    for (int o = 16; o; o >>= 1) {
        ai += __shfl_xor_sync(0xffffffffu, ai, o);
        aj += __shfl_xor_sync(0xffffffffu, aj, o);
    }
    if (!lane) { g_si[gw] = ai; g_sj[gw] = aj; }
}

// ============================================================
// K3: lane-per-edge softmax. 16 lanes per node (one per k),
// reductions via shfl within aligned 16-lane groups.
// ============================================================
__global__ __launch_bounds__(256) void k_softmax(const int* __restrict__ edge,
                                                 const float* __restrict__ ab) {
    const int gt = blockIdx.x * 256 + threadIdx.x;
    const int bn = gt >> 4;              // node
    const int k  = gt & 15;              // neighbor slot
    const int sh = g_is64;               // 0: int32, 1: int64-as-pairs
    const int b  = bn >> 11;
    const size_t ei = (size_t)(bn * Kk + k) << sh;
    const int i0 = edge[ei] & (Nn - 1);
    const int i1 = edge[(((size_t)BN_TOT * Kk) << sh) + ei] & (Nn - 1);
    const float e = g_si[b * Nn + i1] + g_sj[b * Nn + i0] + ab[0];
    float m = e;
    #pragma unroll
    for (int o = 8; o; o >>= 1) m = fmaxf(m, __shfl_xor_sync(0xffffffffu, m, o));
    const float ev = expf(e - m);
    float s = ev;
    #pragma unroll
    for (int o = 8; o; o >>= 1) s += __shfl_xor_sync(0xffffffffu, s, o);
    g_w[bn * Kk + k] = ev / s;
    g_j[bn * Kk + k] = i0;
}

// ============================================================
// K4: neighbor aggregation + interleaved feature build
//     feat[bn, 2c] = xs[bn,c], feat[bn, 2c+1] = agg[bn,c]
// ============================================================
__global__ __launch_bounds__(256) void k_agg() {
    const int node = threadIdx.x >> 6;
    const int t    = threadIdx.x & 63;
    const int bn   = blockIdx.x * 4 + node;
    const int b    = bn >> 11;
    const float* base = g_xsT + (size_t)b * Nn * Cc;
    const int c = t * 4;
    const float4 xc = *(const float4*)(g_xsT + (size_t)bn * Cc + c);
    float ax = 0.f, ay = 0.f, az = 0.f, aw_ = 0.f;
    const float* wp = g_w + bn * Kk;
    const int*   jp = g_j + bn * Kk;
    #pragma unroll
    for (int k = 0; k < Kk; k++) {
        const float wk = wp[k];
        const float4 g = *(const float4*)(base + (size_t)(jp[k] & (Nn - 1)) * Cc + c);
        ax += wk * g.x; ay += wk * g.y; az += wk * g.z; aw_ += wk * g.w;
    }
    float* f = g_feat + (size_t)bn * KD + 2 * c;
    ((float4*)f)[0] = make_float4(xc.x, ax, xc.y, ay);
    ((float4*)f)[1] = make_float4(xc.z, az, xc.w, aw_);
}

// ============================================================
// K5: NT-SGEMM with packed fma.rn.f32x2 (2 FMA/lane/instr)
//     out[b,o,n] = relu( nn_w[o,:] . feat[bn,:] + bias[o] )
//     128x128 tile, BK=8, double-buffered.
//     As holds duplicated rows ({a,a} pairs) so packed A operands
//     load directly; Bs packed pairs are natural adjacent columns.
// ============================================================
__device__ __forceinline__ void fma2(unsigned long long& d,
                                     unsigned long long a,
                                     unsigned long long b) {
    asm("fma.rn.f32x2 %0, %1, %2, %0;" : "+l"(d) : "l"(a), "l"(b));
}

__global__ __launch_bounds__(256)
void k_gemm(const float* __restrict__ A,      // nn_w [256, 512]
            const float* __restrict__ bias,   // nn_b [256]
            float* __restrict__ out) {        // [B, OUT, N]
    __shared__ __align__(16) float As[2][8][256];  // duplicated: [2m]=[2m+1]=A[m]
    __shared__ __align__(16) float Bs[2][8][128];

    const int tid  = threadIdx.x;
    const int m0   = blockIdx.y * 128;
    const int n0   = blockIdx.x * 128;
    const int lrow = tid >> 1;          // 0..127
    const int lcol = (tid & 1) * 4;     // 0 or 4

    const float* Ap = A      + (size_t)(m0 + lrow) * KD + lcol;
    const float* Bp = g_feat + (size_t)(n0 + lrow) * KD + lcol;

    unsigned long long acc[8][4];
    #pragma unroll
    for (int i = 0; i < 8; i++)
        #pragma unroll
        for (int j = 0; j < 4; j++) acc[i][j] = 0ULL;

    {
        const float4 av = *(const float4*)Ap;
        const float4 bv = *(const float4*)Bp;
        *(float2*)&As[0][lcol + 0][2 * lrow] = make_float2(av.x, av.x);
        *(float2*)&As[0][lcol + 1][2 * lrow] = make_float2(av.y, av.y);
        *(float2*)&As[0][lcol + 2][2 * lrow] = make_float2(av.z, av.z);
        *(float2*)&As[0][lcol + 3][2 * lrow] = make_float2(av.w, av.w);
        Bs[0][lcol + 0][lrow] = bv.x;
        Bs[0][lcol + 1][lrow] = bv.y;
        Bs[0][lcol + 2][lrow] = bv.z;
        Bs[0][lcol + 3][lrow] = bv.w;
    }
    __syncthreads();

    const int tx = tid & 15;   // column group (n)
    const int ty = tid >> 4;   // row group (m)

    #pragma unroll 1
    for (int kt = 0; kt < KD / 8; kt++) {
        const int buf = kt & 1;
        float4 av2, bv2;
        if (kt < KD / 8 - 1) {
            av2 = *(const float4*)(Ap + (kt + 1) * 8);
            bv2 = *(const float4*)(Bp + (kt + 1) * 8);
        }
        #pragma unroll
        for (int kk = 0; kk < 8; kk++) {
            const float* arow = As[buf][kk];
            const float* brow = Bs[buf][kk];
            const ulonglong2 a01 = *(const ulonglong2*)(arow + 8 * ty);        // m 4ty..4ty+1
            const ulonglong2 a23 = *(const ulonglong2*)(arow + 8 * ty + 4);    // m 4ty+2..4ty+3
            const ulonglong2 a45 = *(const ulonglong2*)(arow + 8 * ty + 128);  // m 64+4ty..
            const ulonglong2 a67 = *(const ulonglong2*)(arow + 8 * ty + 132);
            const ulonglong2 b01 = *(const ulonglong2*)(brow + 4 * tx);        // n 4tx..4tx+3
            const ulonglong2 b23 = *(const ulonglong2*)(brow + 4 * tx + 64);   // n 64+4tx..
            const unsigned long long aa[8] = {a01.x, a01.y, a23.x, a23.y,
                                              a45.x, a45.y, a67.x, a67.y};
            const unsigned long long bb[4] = {b01.x, b01.y, b23.x, b23.y};
            #pragma unroll
            for (int i = 0; i < 8; i++)
                #pragma unroll
                for (int j = 0; j < 4; j++)
                    fma2(acc[i][j], aa[i], bb[j]);
        }
        if (kt < KD / 8 - 1) {
            const int nbuf = buf ^ 1;
            *(float2*)&As[nbuf][lcol + 0][2 * lrow] = make_float2(av2.x, av2.x);
            *(float2*)&As[nbuf][lcol + 1][2 * lrow] = make_float2(av2.y, av2.y);
            *(float2*)&As[nbuf][lcol + 2][2 * lrow] = make_float2(av2.z, av2.z);
            *(float2*)&As[nbuf][lcol + 3][2 * lrow] = make_float2(av2.w, av2.w);
            Bs[nbuf][lcol + 0][lrow] = bv2.x;
            Bs[nbuf][lcol + 1][lrow] = bv2.y;
            Bs[nbuf][lcol + 2][lrow] = bv2.z;
            Bs[nbuf][lcol + 3][lrow] = bv2.w;
            __syncthreads();
        }
    }

    // epilogue: bias + relu, write out[b, o, n]
    const int bidx = n0 >> 11;             // batch of this 128-col tile
    float* obase = out + (size_t)bidx * OUTd * Nn + (n0 & 2047);
    #pragma unroll
    for (int i = 0; i < 8; i++) {
        const int rloc = (i < 4) ? (4 * ty + i) : (64 + 4 * ty + (i - 4));
        const int row  = m0 + rloc;
        const float bv = bias[row];
        float v[8];
        #pragma unroll
        for (int j = 0; j < 4; j++) {
            const unsigned long long p = acc[i][j];
            v[2 * j]     = __uint_as_float((unsigned)(p & 0xffffffffu));
            v[2 * j + 1] = __uint_as_float((unsigned)(p >> 32));
        }
        float4 o0, o1;
        o0.x = fmaxf(v[0] + bv, 0.f);
        o0.y = fmaxf(v[1] + bv, 0.f);
        o0.z = fmaxf(v[2] + bv, 0.f);
        o0.w = fmaxf(v[3] + bv, 0.f);
        o1.x = fmaxf(v[4] + bv, 0.f);
        o1.y = fmaxf(v[5] + bv, 0.f);
        o1.z = fmaxf(v[6] + bv, 0.f);
        o1.w = fmaxf(v[7] + bv, 0.f);
        *(float4*)(obase + (size_t)row * Nn + 4 * tx)      = o0;
        *(float4*)(obase + (size_t)row * Nn + 64 + 4 * tx) = o1;
    }
}

// ============================================================
// launch
// ============================================================
extern "C" void kernel_launch(void* const* d_in, const int* in_sizes, int n_in,
                              void* d_out, int out_size) {
    const float* x    = (const float*)d_in[0];
    const int*   edge = (const int*)d_in[1];
    const float* a_w  = (const float*)d_in[2];
    const float* a_b  = (const float*)d_in[3];
    const float* nn_w = (const float*)d_in[4];
    const float* nn_b = (const float*)d_in[5];
    float*       out  = (float*)d_out;

    k_detect  <<<1, 32>>>(edge);
    k_transpose<<<dim3(Nn / 32, Cc / 32, Bb), dim3(32, 8)>>>(x);
    k_scores  <<<(BN_TOT * 32) / 256, 256>>>(a_w);
    k_softmax <<<(BN_TOT * Kk) / 256, 256>>>(edge, a_b);
    k_agg     <<<BN_TOT / 4, 256>>>();
    k_gemm    <<<dim3(BN_TOT / 128, OUTd / 128), 256>>>(nn_w, nn_b, out);
}

// round 7
// speedup vs baseline: 1.6208x; 1.6208x over previous
#include <cuda_runtime.h>
#include <cuda_bf16.h>
#include <cstdint>

// Problem constants
#define Bb   8
#define Cc   256
#define Nn   2048
#define Kk   16
#define OUTd 256
#define KD   512                 // 2*C
#define BN_TOT (Bb*Nn)           // 16384
#define NTILES 128               // 16384/128
#define MTILES 2                 // 256/128

// ---- scratch (static device globals; no dynamic allocation) ----
__device__ float g_xsT [BN_TOT * Cc];   // [B*N, C] node-major features
__device__ float g_si  [BN_TOT];
__device__ float g_sj  [BN_TOT];
__device__ float g_w   [BN_TOT * Kk];   // softmax weights
__device__ int   g_j   [BN_TOT * Kk];   // neighbor indices (int32)
__device__ int   g_is64;                // 1 if edge buffer is int64 viewed as int32 pairs

// bf16 hi/lo split operands, plain row-major [rows][512]
__device__ __nv_bfloat16 g_FH[(size_t)BN_TOT * KD];
__device__ __nv_bfloat16 g_FL[(size_t)BN_TOT * KD];
__device__ __nv_bfloat16 g_WH[(size_t)OUTd * KD];
__device__ __nv_bfloat16 g_WL[(size_t)OUTd * KD];

// ============================================================
// helpers
// ============================================================
__device__ __forceinline__ uint32_t smem_u32(const void* p) {
    uint32_t a;
    asm("{ .reg .u64 t; cvta.to.shared.u64 t, %1; cvt.u32.u64 %0, t; }"
        : "=r"(a) : "l"(p));
    return a;
}
__device__ __forceinline__ void ldm4(uint32_t* r, uint32_t addr) {
    asm volatile("ldmatrix.sync.aligned.m8n8.x4.shared.b16 {%0,%1,%2,%3}, [%4];"
                 : "=r"(r[0]), "=r"(r[1]), "=r"(r[2]), "=r"(r[3]) : "r"(addr));
}
__device__ __forceinline__ void mma16816(float* d, const uint32_t* a,
                                         const uint32_t* b) {
    asm volatile(
        "mma.sync.aligned.m16n8k16.row.col.f32.bf16.bf16.f32 "
        "{%0,%1,%2,%3}, {%4,%5,%6,%7}, {%8,%9}, {%0,%1,%2,%3};"
        : "+f"(d[0]), "+f"(d[1]), "+f"(d[2]), "+f"(d[3])
        : "r"(a[0]), "r"(a[1]), "r"(a[2]), "r"(a[3]), "r"(b[0]), "r"(b[1]));
}

// ============================================================
// K0: detect edge dtype (int64 viewed as int32 pairs has zero odd words)
// ============================================================
__global__ void k_detect(const int* __restrict__ e) {
    const int t = threadIdx.x;
    int bad = 0;
    #pragma unroll
    for (int i = t; i < 256; i += 32) bad |= e[2 * i + 1];
    #pragma unroll
    for (int o = 16; o; o >>= 1) bad |= __shfl_xor_sync(0xffffffffu, bad, o);
    if (!t) g_is64 = (bad == 0) ? 1 : 0;
}

// ============================================================
// K1: transpose xs [B,C,N] -> xsT [B*N, C]
// ============================================================
__global__ void k_transpose(const float* __restrict__ x) {
    __shared__ float tile[32][33];
    const int b  = blockIdx.z;
    const int n0 = blockIdx.x * 32;
    const int c0 = blockIdx.y * 32;
    const float* xb = x + (size_t)b * Cc * Nn;
    #pragma unroll
    for (int i = 0; i < 32; i += 8)
        tile[threadIdx.y + i][threadIdx.x] =
            xb[(size_t)(c0 + threadIdx.y + i) * Nn + n0 + threadIdx.x];
    __syncthreads();
    float* xt = g_xsT + (size_t)b * Nn * Cc;
    #pragma unroll
    for (int i = 0; i < 32; i += 8)
        xt[(size_t)(n0 + threadIdx.y + i) * Cc + c0 + threadIdx.x] =
            tile[threadIdx.x][threadIdx.y + i];
}

// ============================================================
// K2: per-node attention pre-scores s_i, s_j (one warp per node)
// ============================================================
__global__ void k_scores(const float* __restrict__ aw) {
    const int gw   = (blockIdx.x * blockDim.x + threadIdx.x) >> 5;
    const int lane = threadIdx.x & 31;
    if (gw >= BN_TOT) return;
    const float4* v  = (const float4*)(g_xsT + (size_t)gw * Cc);
    const float4* wi = (const float4*)aw;
    const float4* wj = (const float4*)(aw + Cc);
    float ai = 0.f, aj = 0.f;
    #pragma unroll
    for (int r = 0; r < 2; r++) {
        const int idx = lane + r * 32;
        float4 xv = v[idx], w1 = wi[idx], w2 = wj[idx];
        ai += xv.x * w1.x + xv.y * w1.y + xv.z * w1.z + xv.w * w1.w;
        aj += xv.x * w2.x + xv.y * w2.y + xv.z * w2.z + xv.w * w2.w;
    }
    #pragma unroll
    for (int o = 16; o; o >>= 1) {
        ai += __shfl_xor_sync(0xffffffffu, ai, o);
        aj += __shfl_xor_sync(0xffffffffu, aj, o);
    }
    if (!lane) { g_si[gw] = ai; g_sj[gw] = aj; }
}

// ============================================================
// K3: lane-per-edge softmax (16 lanes per node)
// ============================================================
__global__ __launch_bounds__(256) void k_softmax(const int* __restrict__ edge,
                                                 const float* __restrict__ ab) {
    const int gt = blockIdx.x * 256 + threadIdx.x;
    const int bn = gt >> 4;
    const int k  = gt & 15;
    const int sh = g_is64;
    const int b  = bn >> 11;
    const size_t ei = (size_t)(bn * Kk + k) << sh;
    const int i0 = edge[ei] & (Nn - 1);
    const int i1 = edge[(((size_t)BN_TOT * Kk) << sh) + ei] & (Nn - 1);
    const float e = g_si[b * Nn + i1] + g_sj[b * Nn + i0] + ab[0];
    float m = e;
    #pragma unroll
    for (int o = 8; o; o >>= 1) m = fmaxf(m, __shfl_xor_sync(0xffffffffu, m, o));
    const float ev = expf(e - m);
    float s = ev;
    #pragma unroll
    for (int o = 8; o; o >>= 1) s += __shfl_xor_sync(0xffffffffu, s, o);
    g_w[bn * Kk + k] = ev / s;
    g_j[bn * Kk + k] = i0;
}

// ============================================================
// K4: aggregation + interleave + bf16 hi/lo split (row-major)
// ============================================================
__global__ __launch_bounds__(256) void k_agg() {
    const int node = threadIdx.x >> 6;
    const int t    = threadIdx.x & 63;       // channel group: feat f = 8t..8t+7
    const int bn   = blockIdx.x * 4 + node;
    const int b    = bn >> 11;
    const float* base = g_xsT + (size_t)b * Nn * Cc;
    const int c = t * 4;
    const float4 xc = *(const float4*)(g_xsT + (size_t)bn * Cc + c);
    float ax = 0.f, ay = 0.f, az = 0.f, aw_ = 0.f;
    const float* wp = g_w + bn * Kk;
    const int*   jp = g_j + bn * Kk;
    #pragma unroll
    for (int k = 0; k < Kk; k++) {
        const float wk = wp[k];
        const float4 g = *(const float4*)(base + (size_t)(jp[k] & (Nn - 1)) * Cc + c);
        ax += wk * g.x; ay += wk * g.y; az += wk * g.z; aw_ += wk * g.w;
    }
    const float v[8] = {xc.x, ax, xc.y, ay, xc.z, az, xc.w, aw_};
    union { uint4 u; __nv_bfloat16 h[8]; } H, L;
    #pragma unroll
    for (int j = 0; j < 8; j++) {
        H.h[j] = __float2bfloat16(v[j]);
        L.h[j] = __float2bfloat16(v[j] - __bfloat162float(H.h[j]));
    }
    const size_t o = (size_t)bn * KD + 8 * t;
    *(uint4*)(g_FH + o) = H.u;
    *(uint4*)(g_FL + o) = L.u;
}

// ============================================================
// K4b: weight hi/lo split (row-major)
// ============================================================
__global__ void k_wsplit(const float* __restrict__ W) {
    const int gid = blockIdx.x * 256 + threadIdx.x;
    const int o = gid >> 6;          // 0..255
    const int g = gid & 63;          // 8-channel group
    const float* wp = W + (size_t)o * KD + g * 8;
    union { uint4 u; __nv_bfloat16 h[8]; } H, L;
    #pragma unroll
    for (int j = 0; j < 8; j++) {
        const float w = wp[j];
        H.h[j] = __float2bfloat16(w);
        L.h[j] = __float2bfloat16(w - __bfloat162float(H.h[j]));
    }
    const size_t off = (size_t)o * KD + 8 * g;
    *(uint4*)(g_WH + off) = H.u;
    *(uint4*)(g_WL + off) = L.u;
}

// ============================================================
// K5: bf16-split GEMM via mma.sync.m16n8k16 (3 passes)
//     D[o,n] = sum_k W[o,k]*F[n,k];  CTA tile 128x128, BK=16,
//     8 warps (64x32 warp tiles), double-buffered static smem.
// ============================================================
#define PITCH 24                              // bf16 row pitch (48B, 16B-aligned rows, conflict-free)

__global__ __launch_bounds__(256, 1)
void k_gemm_mma(const float* __restrict__ bias, float* __restrict__ out) {
    __shared__ __align__(16) __nv_bfloat16 sm[2][4][128][PITCH];  // AH, AL, BH, BL

    const int tid  = threadIdx.x;
    const int lane = tid & 31;
    const int warp = tid >> 5;
    const int wm   = warp >> 2;     // 0..1
    const int wn   = warp & 3;      // 0..3
    const int nt   = blockIdx.x;    // 0..127
    const int mt   = blockIdx.y;    // 0..1

    // staging: thread loads one uint4 (8 bf16) per array per stage
    const int lrow  = tid >> 1;     // 0..127
    const int lhalf = tid & 1;      // k-chunk within stage
    const __nv_bfloat16* pWH = g_WH + (size_t)(mt * 128 + lrow) * KD + lhalf * 8;
    const __nv_bfloat16* pWL = g_WL + (size_t)(mt * 128 + lrow) * KD + lhalf * 8;
    const __nv_bfloat16* pFH = g_FH + (size_t)(nt * 128 + lrow) * KD + lhalf * 8;
    const __nv_bfloat16* pFL = g_FL + (size_t)(nt * 128 + lrow) * KD + lhalf * 8;

    // prologue: stage 0
    {
        const uint4 a = *(const uint4*)pWH;
        const uint4 b = *(const uint4*)pWL;
        const uint4 c = *(const uint4*)pFH;
        const uint4 d = *(const uint4*)pFL;
        *(uint4*)&sm[0][0][lrow][lhalf * 8] = a;
        *(uint4*)&sm[0][1][lrow][lhalf * 8] = b;
        *(uint4*)&sm[0][2][lrow][lhalf * 8] = c;
        *(uint4*)&sm[0][3][lrow][lhalf * 8] = d;
    }
    __syncthreads();

    float acc[4][4][4];
    #pragma unroll
    for (int i = 0; i < 4; i++)
        #pragma unroll
        for (int j = 0; j < 4; j++)
            #pragma unroll
            for (int q = 0; q < 4; q++) acc[i][j][q] = 0.f;

    // per-lane ldmatrix row/chunk (A and B patterns)
    const int arow = wm * 64 + (lane & 7) + ((lane >> 3) & 1) * 8;  // + mf*16
    const int achk = ((lane >> 4) & 1) * 8;
    const int brow = wn * 32 + ((lane >> 4) & 1) * 8 + (lane & 7);  // + p*16
    const int bchk = ((lane >> 3) & 1) * 8;

    #pragma unroll 1
    for (int kt = 0; kt < KD / 16; kt++) {
        const int buf = kt & 1;
        uint4 nA, nB, nC, nD;
        if (kt < KD / 16 - 1) {
            const int ko = (kt + 1) * 16;
            nA = *(const uint4*)(pWH + ko);
            nB = *(const uint4*)(pWL + ko);
            nC = *(const uint4*)(pFH + ko);
            nD = *(const uint4*)(pFL + ko);
        }

        uint32_t ah[4][4], al[4][4], bhf[4][2], blf[4][2];
        #pragma unroll
        for (int mf = 0; mf < 4; mf++) {
            ldm4(ah[mf], smem_u32(&sm[buf][0][arow + mf * 16][achk]));
            ldm4(al[mf], smem_u32(&sm[buf][1][arow + mf * 16][achk]));
        }
        #pragma unroll
        for (int p = 0; p < 2; p++) {
            uint32_t r[4];
            ldm4(r, smem_u32(&sm[buf][2][brow + p * 16][bchk]));
            bhf[2 * p][0] = r[0]; bhf[2 * p][1] = r[1];
            bhf[2 * p + 1][0] = r[2]; bhf[2 * p + 1][1] = r[3];
            ldm4(r, smem_u32(&sm[buf][3][brow + p * 16][bchk]));
            blf[2 * p][0] = r[0]; blf[2 * p][1] = r[1];
            blf[2 * p + 1][0] = r[2]; blf[2 * p + 1][1] = r[3];
        }
        #pragma unroll
        for (int mf = 0; mf < 4; mf++)
            #pragma unroll
            for (int nf = 0; nf < 4; nf++) {
                mma16816(acc[mf][nf], ah[mf], bhf[nf]);   // hi*hi
                mma16816(acc[mf][nf], ah[mf], blf[nf]);   // hi*lo
                mma16816(acc[mf][nf], al[mf], bhf[nf]);   // lo*hi
            }

        if (kt < KD / 16 - 1) {
            const int nb = buf ^ 1;
            *(uint4*)&sm[nb][0][lrow][lhalf * 8] = nA;
            *(uint4*)&sm[nb][1][lrow][lhalf * 8] = nB;
            *(uint4*)&sm[nb][2][lrow][lhalf * 8] = nC;
            *(uint4*)&sm[nb][3][lrow][lhalf * 8] = nD;
        }
        __syncthreads();
    }

    // epilogue: bias + relu
    const int g    = lane >> 2;
    const int tig  = lane & 3;
    const int bidx = nt >> 4;
    const int nb0  = (nt & 15) * 128 + wn * 32 + 2 * tig;
    #pragma unroll
    for (int mf = 0; mf < 4; mf++) {
        const int o0  = mt * 128 + wm * 64 + mf * 16 + g;
        const float b0 = bias[o0];
        const float b1 = bias[o0 + 8];
        float* r0 = out + ((size_t)(bidx * OUTd + o0) * Nn);
        float* r1 = out + ((size_t)(bidx * OUTd + o0 + 8) * Nn);
        #pragma unroll
        for (int nf = 0; nf < 4; nf++) {
            const int nb = nb0 + nf * 8;
            float2 w0, w1;
            w0.x = fmaxf(acc[mf][nf][0] + b0, 0.f);
            w0.y = fmaxf(acc[mf][nf][1] + b0, 0.f);
            w1.x = fmaxf(acc[mf][nf][2] + b1, 0.f);
            w1.y = fmaxf(acc[mf][nf][3] + b1, 0.f);
            *(float2*)(r0 + nb) = w0;
            *(float2*)(r1 + nb) = w1;
        }
    }
}

// ============================================================
// launch
// ============================================================
extern "C" void kernel_launch(void* const* d_in, const int* in_sizes, int n_in,
                              void* d_out, int out_size) {
    const float* x    = (const float*)d_in[0];
    const int*   edge = (const int*)d_in[1];
    const float* a_w  = (const float*)d_in[2];
    const float* a_b  = (const float*)d_in[3];
    const float* nn_w = (const float*)d_in[4];
    const float* nn_b = (const float*)d_in[5];
    float*       out  = (float*)d_out;

    k_detect   <<<1, 32>>>(edge);
    k_transpose<<<dim3(Nn / 32, Cc / 32, Bb), dim3(32, 8)>>>(x);
    k_scores   <<<(BN_TOT * 32) / 256, 256>>>(a_w);
    k_softmax  <<<(BN_TOT * Kk) / 256, 256>>>(edge, a_b);
    k_wsplit   <<<64, 256>>>(nn_w);
    k_agg      <<<BN_TOT / 4, 256>>>();
    k_gemm_mma <<<dim3(NTILES, MTILES), 256>>>(nn_b, out);
}

// round 8
// speedup vs baseline: 1.6878x; 1.0413x over previous
#include <cuda_runtime.h>
#include <cuda_bf16.h>
#include <cstdint>

// Problem constants
#define Bb   8
#define Cc   256
#define Nn   2048
#define Kk   16
#define OUTd 256
#define KD   512                 // 2*C
#define BN_TOT (Bb*Nn)           // 16384
#define NTILES 128               // 16384/128
#define MTILES 2                 // 256/128

// ---- scratch (static device globals; no dynamic allocation) ----
__device__ float         g_xsT[BN_TOT * Cc];  // [B*N, C] fp32 node-major
__device__ __nv_bfloat16 g_xsB[BN_TOT * Cc];  // bf16 copy for neighbor gathers
__device__ float g_si  [BN_TOT];
__device__ float g_sj  [BN_TOT];
__device__ float g_w   [BN_TOT * Kk];
__device__ int   g_j   [BN_TOT * Kk];
__device__ int   g_is64;

// bf16 hi/lo split operands, row-major [rows][512]
__device__ __nv_bfloat16 g_FH[(size_t)BN_TOT * KD];
__device__ __nv_bfloat16 g_FL[(size_t)BN_TOT * KD];
__device__ __nv_bfloat16 g_WH[(size_t)OUTd * KD];
__device__ __nv_bfloat16 g_WL[(size_t)OUTd * KD];

// ============================================================
// helpers
// ============================================================
__device__ __forceinline__ uint32_t smem_u32(const void* p) {
    uint32_t a;
    asm("{ .reg .u64 t; cvta.to.shared.u64 t, %1; cvt.u32.u64 %0, t; }"
        : "=r"(a) : "l"(p));
    return a;
}
__device__ __forceinline__ void ldm4(uint32_t* r, uint32_t addr) {
    asm volatile("ldmatrix.sync.aligned.m8n8.x4.shared.b16 {%0,%1,%2,%3}, [%4];"
                 : "=r"(r[0]), "=r"(r[1]), "=r"(r[2]), "=r"(r[3]) : "r"(addr));
}
__device__ __forceinline__ void mma16816(float* d, const uint32_t* a,
                                         const uint32_t* b) {
    asm volatile(
        "mma.sync.aligned.m16n8k16.row.col.f32.bf16.bf16.f32 "
        "{%0,%1,%2,%3}, {%4,%5,%6,%7}, {%8,%9}, {%0,%1,%2,%3};"
        : "+f"(d[0]), "+f"(d[1]), "+f"(d[2]), "+f"(d[3])
        : "r"(a[0]), "r"(a[1]), "r"(a[2]), "r"(a[3]), "r"(b[0]), "r"(b[1]));
}
#define CP16(dst, src) asm volatile("cp.async.cg.shared.global [%0], [%1], 16;" :: "r"(dst), "l"(src))
#define CP_COMMIT()    asm volatile("cp.async.commit_group;" ::: "memory")
#define CP_WAIT1()     asm volatile("cp.async.wait_group 1;" ::: "memory")
#define CP_WAIT0()     asm volatile("cp.async.wait_group 0;" ::: "memory")

// ============================================================
// K0: detect edge dtype
// ============================================================
__global__ void k_detect(const int* __restrict__ e) {
    const int t = threadIdx.x;
    int bad = 0;
    #pragma unroll
    for (int i = t; i < 256; i += 32) bad |= e[2 * i + 1];
    #pragma unroll
    for (int o = 16; o; o >>= 1) bad |= __shfl_xor_sync(0xffffffffu, bad, o);
    if (!t) g_is64 = (bad == 0) ? 1 : 0;
}

// ============================================================
// K1: transpose xs [B,C,N] -> xsT (fp32) + xsB (bf16)
// ============================================================
__global__ void k_transpose(const float* __restrict__ x) {
    __shared__ float tile[32][33];
    const int b  = blockIdx.z;
    const int n0 = blockIdx.x * 32;
    const int c0 = blockIdx.y * 32;
    const float* xb = x + (size_t)b * Cc * Nn;
    #pragma unroll
    for (int i = 0; i < 32; i += 8)
        tile[threadIdx.y + i][threadIdx.x] =
            xb[(size_t)(c0 + threadIdx.y + i) * Nn + n0 + threadIdx.x];
    __syncthreads();
    float*         xt  = g_xsT + (size_t)b * Nn * Cc;
    __nv_bfloat16* xt2 = g_xsB + (size_t)b * Nn * Cc;
    #pragma unroll
    for (int i = 0; i < 32; i += 8) {
        const float v = tile[threadIdx.x][threadIdx.y + i];
        const size_t o = (size_t)(n0 + threadIdx.y + i) * Cc + c0 + threadIdx.x;
        xt[o]  = v;
        xt2[o] = __float2bfloat16(v);
    }
}

// ============================================================
// K2: per-node attention pre-scores (one warp per node)
// ============================================================
__global__ void k_scores(const float* __restrict__ aw) {
    const int gw   = (blockIdx.x * blockDim.x + threadIdx.x) >> 5;
    const int lane = threadIdx.x & 31;
    if (gw >= BN_TOT) return;
    const float4* v  = (const float4*)(g_xsT + (size_t)gw * Cc);
    const float4* wi = (const float4*)aw;
    const float4* wj = (const float4*)(aw + Cc);
    float ai = 0.f, aj = 0.f;
    #pragma unroll
    for (int r = 0; r < 2; r++) {
        const int idx = lane + r * 32;
        float4 xv = v[idx], w1 = wi[idx], w2 = wj[idx];
        ai += xv.x * w1.x + xv.y * w1.y + xv.z * w1.z + xv.w * w1.w;
        aj += xv.x * w2.x + xv.y * w2.y + xv.z * w2.z + xv.w * w2.w;
    }
    #pragma unroll
    for (int o = 16; o; o >>= 1) {
        ai += __shfl_xor_sync(0xffffffffu, ai, o);
        aj += __shfl_xor_sync(0xffffffffu, aj, o);
    }
    if (!lane) { g_si[gw] = ai; g_sj[gw] = aj; }
}

// ============================================================
// K3: lane-per-edge softmax (16 lanes per node)
// ============================================================
__global__ __launch_bounds__(256) void k_softmax(const int* __restrict__ edge,
                                                 const float* __restrict__ ab) {
    const int gt = blockIdx.x * 256 + threadIdx.x;
    const int bn = gt >> 4;
    const int k  = gt & 15;
    const int sh = g_is64;
    const int b  = bn >> 11;
    const size_t ei = (size_t)(bn * Kk + k) << sh;
    const int i0 = edge[ei] & (Nn - 1);
    const int i1 = edge[(((size_t)BN_TOT * Kk) << sh) + ei] & (Nn - 1);
    const float e = g_si[b * Nn + i1] + g_sj[b * Nn + i0] + ab[0];
    float m = e;
    #pragma unroll
    for (int o = 8; o; o >>= 1) m = fmaxf(m, __shfl_xor_sync(0xffffffffu, m, o));
    const float ev = expf(e - m);
    float s = ev;
    #pragma unroll
    for (int o = 8; o; o >>= 1) s += __shfl_xor_sync(0xffffffffu, s, o);
    g_w[bn * Kk + k] = ev / s;
    g_j[bn * Kk + k] = i0;
}

// ============================================================
// K4: aggregation (bf16 gathers, fp32 accum) + interleave +
//     bf16 hi/lo split (row-major)
// ============================================================
__global__ __launch_bounds__(256) void k_agg() {
    const int node = threadIdx.x >> 6;
    const int t    = threadIdx.x & 63;       // channel group c = 4t
    const int bn   = blockIdx.x * 4 + node;
    const int b    = bn >> 11;
    const uint2* base = (const uint2*)(g_xsB + (size_t)b * Nn * Cc);  // 64 uint2 per row
    const int c = t * 4;
    const float4 xc = *(const float4*)(g_xsT + (size_t)bn * Cc + c);  // exact center
    float ax = 0.f, ay = 0.f, az = 0.f, aw_ = 0.f;
    const float* wp = g_w + bn * Kk;
    const int*   jp = g_j + bn * Kk;
    #pragma unroll
    for (int k = 0; k < Kk; k++) {
        const float wk = wp[k];
        const uint2 raw = base[(size_t)(jp[k] & (Nn - 1)) * 64 + t];
        const float2 p0 = __bfloat1622float2(*(const __nv_bfloat162*)&raw.x);
        const float2 p1 = __bfloat1622float2(*(const __nv_bfloat162*)&raw.y);
        ax += wk * p0.x; ay += wk * p0.y; az += wk * p1.x; aw_ += wk * p1.y;
    }
    const float v[8] = {xc.x, ax, xc.y, ay, xc.z, az, xc.w, aw_};
    union { uint4 u; __nv_bfloat16 h[8]; } H, L;
    #pragma unroll
    for (int j = 0; j < 8; j++) {
        H.h[j] = __float2bfloat16(v[j]);
        L.h[j] = __float2bfloat16(v[j] - __bfloat162float(H.h[j]));
    }
    const size_t o = (size_t)bn * KD + 8 * t;
    *(uint4*)(g_FH + o) = H.u;
    *(uint4*)(g_FL + o) = L.u;
}

// ============================================================
// K4b: weight hi/lo split (row-major)
// ============================================================
__global__ void k_wsplit(const float* __restrict__ W) {
    const int gid = blockIdx.x * 256 + threadIdx.x;
    const int o = gid >> 6;
    const int g = gid & 63;
    const float* wp = W + (size_t)o * KD + g * 8;
    union { uint4 u; __nv_bfloat16 h[8]; } H, L;
    #pragma unroll
    for (int j = 0; j < 8; j++) {
        const float w = wp[j];
        H.h[j] = __float2bfloat16(w);
        L.h[j] = __float2bfloat16(w - __bfloat162float(H.h[j]));
    }
    const size_t off = (size_t)o * KD + 8 * g;
    *(uint4*)(g_WH + off) = H.u;
    *(uint4*)(g_WL + off) = L.u;
}

// ============================================================
// K5: bf16-split GEMM via mma.sync (3 passes), cp.async
//     double-buffered, 2 CTAs/SM. CTA 128x128, BK=16, 8 warps.
// ============================================================
#define PITCH 24

__global__ __launch_bounds__(256, 2)
void k_gemm_mma(const float* __restrict__ bias, float* __restrict__ out) {
    __shared__ __align__(16) __nv_bfloat16 sm[2][4][128][PITCH];  // WH, WL, FH, FL

    const int tid  = threadIdx.x;
    const int lane = tid & 31;
    const int warp = tid >> 5;
    const int wm   = warp >> 2;     // 0..1
    const int wn   = warp & 3;      // 0..3
    const int nt   = blockIdx.x;
    const int mt   = blockIdx.y;

    const int lrow  = tid >> 1;
    const int lhalf = tid & 1;
    const __nv_bfloat16* pWH = g_WH + (size_t)(mt * 128 + lrow) * KD + lhalf * 8;
    const __nv_bfloat16* pWL = g_WL + (size_t)(mt * 128 + lrow) * KD + lhalf * 8;
    const __nv_bfloat16* pFH = g_FH + (size_t)(nt * 128 + lrow) * KD + lhalf * 8;
    const __nv_bfloat16* pFL = g_FL + (size_t)(nt * 128 + lrow) * KD + lhalf * 8;
    const uint32_t dWH = smem_u32(&sm[0][0][lrow][lhalf * 8]);
    const uint32_t dWL = smem_u32(&sm[0][1][lrow][lhalf * 8]);
    const uint32_t dFH = smem_u32(&sm[0][2][lrow][lhalf * 8]);
    const uint32_t dFL = smem_u32(&sm[0][3][lrow][lhalf * 8]);
    const uint32_t BUFB = 4 * 128 * PITCH * 2;   // bytes per buffer

    // prologue: stages 0 and 1 in flight
    #pragma unroll
    for (int s = 0; s < 2; s++) {
        const int ko = s * 16;
        const uint32_t bo = s * BUFB;
        CP16(dWH + bo, pWH + ko);
        CP16(dWL + bo, pWL + ko);
        CP16(dFH + bo, pFH + ko);
        CP16(dFL + bo, pFL + ko);
        CP_COMMIT();
    }

    float acc[4][4][4];
    #pragma unroll
    for (int i = 0; i < 4; i++)
        #pragma unroll
        for (int j = 0; j < 4; j++)
            #pragma unroll
            for (int q = 0; q < 4; q++) acc[i][j][q] = 0.f;

    const int arow = wm * 64 + (lane & 7) + ((lane >> 3) & 1) * 8;
    const int achk = ((lane >> 4) & 1) * 8;
    const int brow = wn * 32 + ((lane >> 4) & 1) * 8 + (lane & 7);
    const int bchk = ((lane >> 3) & 1) * 8;

    #pragma unroll 1
    for (int kt = 0; kt < KD / 16; kt++) {
        const int buf = kt & 1;
        if (kt < KD / 16 - 1) CP_WAIT1(); else CP_WAIT0();
        __syncthreads();

        uint32_t bhf[4][2], blf[4][2];
        #pragma unroll
        for (int p = 0; p < 2; p++) {
            uint32_t r[4];
            ldm4(r, smem_u32(&sm[buf][2][brow + p * 16][bchk]));
            bhf[2 * p][0] = r[0]; bhf[2 * p][1] = r[1];
            bhf[2 * p + 1][0] = r[2]; bhf[2 * p + 1][1] = r[3];
            ldm4(r, smem_u32(&sm[buf][3][brow + p * 16][bchk]));
            blf[2 * p][0] = r[0]; blf[2 * p][1] = r[1];
            blf[2 * p + 1][0] = r[2]; blf[2 * p + 1][1] = r[3];
        }
        #pragma unroll
        for (int mf = 0; mf < 4; mf++) {
            uint32_t ah[4], al[4];
            ldm4(ah, smem_u32(&sm[buf][0][arow + mf * 16][achk]));
            ldm4(al, smem_u32(&sm[buf][1][arow + mf * 16][achk]));
            #pragma unroll
            for (int nf = 0; nf < 4; nf++) {
                mma16816(acc[mf][nf], ah, bhf[nf]);
                mma16816(acc[mf][nf], ah, blf[nf]);
                mma16816(acc[mf][nf], al, bhf[nf]);
            }
        }
        __syncthreads();
        if (kt + 2 < KD / 16) {
            const int ko = (kt + 2) * 16;
            const uint32_t bo = buf * BUFB;
            CP16(dWH + bo, pWH + ko);
            CP16(dWL + bo, pWL + ko);
            CP16(dFH + bo, pFH + ko);
            CP16(dFL + bo, pFL + ko);
            CP_COMMIT();
        }
    }

    // epilogue: bias + relu
    const int g    = lane >> 2;
    const int tig  = lane & 3;
    const int bidx = nt >> 4;
    const int nb0  = (nt & 15) * 128 + wn * 32 + 2 * tig;
    #pragma unroll
    for (int mf = 0; mf < 4; mf++) {
        const int o0  = mt * 128 + wm * 64 + mf * 16 + g;
        const float b0 = bias[o0];
        const float b1 = bias[o0 + 8];
        float* r0 = out + ((size_t)(bidx * OUTd + o0) * Nn);
        float* r1 = out + ((size_t)(bidx * OUTd + o0 + 8) * Nn);
        #pragma unroll
        for (int nf = 0; nf < 4; nf++) {
            const int nb = nb0 + nf * 8;
            float2 w0, w1;
            w0.x = fmaxf(acc[mf][nf][0] + b0, 0.f);
            w0.y = fmaxf(acc[mf][nf][1] + b0, 0.f);
            w1.x = fmaxf(acc[mf][nf][2] + b1, 0.f);
            w1.y = fmaxf(acc[mf][nf][3] + b1, 0.f);
            *(float2*)(r0 + nb) = w0;
            *(float2*)(r1 + nb) = w1;
        }
    }
}

// ============================================================
// launch
// ============================================================
extern "C" void kernel_launch(void* const* d_in, const int* in_sizes, int n_in,
                              void* d_out, int out_size) {
    const float* x    = (const float*)d_in[0];
    const int*   edge = (const int*)d_in[1];
    const float* a_w  = (const float*)d_in[2];
    const float* a_b  = (const float*)d_in[3];
    const float* nn_w = (const float*)d_in[4];
    const float* nn_b = (const float*)d_in[5];
    float*       out  = (float*)d_out;

    k_detect   <<<1, 32>>>(edge);
    k_transpose<<<dim3(Nn / 32, Cc / 32, Bb), dim3(32, 8)>>>(x);
    k_scores   <<<(BN_TOT * 32) / 256, 256>>>(a_w);
    k_softmax  <<<(BN_TOT * Kk) / 256, 256>>>(edge, a_b);
    k_wsplit   <<<64, 256>>>(nn_w);
    k_agg      <<<BN_TOT / 4, 256>>>();
    k_gemm_mma <<<dim3(NTILES, MTILES), 256>>>(nn_b, out);
}

// round 9
// speedup vs baseline: 2.0773x; 1.2308x over previous
#include <cuda_runtime.h>
#include <cuda_fp16.h>
#include <cstdint>

// Problem constants
#define Bb   8
#define Cc   256
#define Nn   2048
#define Kk   16
#define OUTd 256
#define KD   512                 // 2*C
#define BN_TOT (Bb*Nn)           // 16384
#define NTILES 128               // 16384/128
#define MTILES 2                 // 256/128

// ---- scratch (static device globals; no dynamic allocation) ----
__device__ float  g_xsT[BN_TOT * Cc];   // [B*N, C] fp32 node-major
__device__ __half g_xsH[BN_TOT * Cc];   // fp16 copy for neighbor gathers
__device__ float g_si [BN_TOT];
__device__ float g_sj [BN_TOT];
__device__ float g_w  [BN_TOT * Kk];
__device__ int   g_j  [BN_TOT * Kk];
__device__ int   g_is64;

// int8 split operands (Q = qh*128 + ql, |Q| <= 16256), row-major [rows][512]
__device__ signed char g_FQh[(size_t)BN_TOT * KD];
__device__ signed char g_FQl[(size_t)BN_TOT * KD];
__device__ signed char g_WQh[(size_t)OUTd * KD];
__device__ signed char g_WQl[(size_t)OUTd * KD];
__device__ float g_sf[BN_TOT];          // per-feature-row scale
__device__ float g_sa[OUTd];            // per-weight-row scale

// ============================================================
// helpers
// ============================================================
__device__ __forceinline__ uint32_t smem_u32(const void* p) {
    uint32_t a;
    asm("{ .reg .u64 t; cvta.to.shared.u64 t, %1; cvt.u32.u64 %0, t; }"
        : "=r"(a) : "l"(p));
    return a;
}
__device__ __forceinline__ void ldm4(uint32_t* r, uint32_t addr) {
    asm volatile("ldmatrix.sync.aligned.m8n8.x4.shared.b16 {%0,%1,%2,%3}, [%4];"
                 : "=r"(r[0]), "=r"(r[1]), "=r"(r[2]), "=r"(r[3]) : "r"(addr));
}
__device__ __forceinline__ void imma(int* d, const uint32_t* a, const uint32_t* b) {
    asm volatile(
        "mma.sync.aligned.m16n8k32.row.col.s32.s8.s8.s32 "
        "{%0,%1,%2,%3}, {%4,%5,%6,%7}, {%8,%9}, {%0,%1,%2,%3};"
        : "+r"(d[0]), "+r"(d[1]), "+r"(d[2]), "+r"(d[3])
        : "r"(a[0]), "r"(a[1]), "r"(a[2]), "r"(a[3]), "r"(b[0]), "r"(b[1]));
}
#define CP16(dst, src) asm volatile("cp.async.cg.shared.global [%0], [%1], 16;" :: "r"(dst), "l"(src))
#define CP_COMMIT()    asm volatile("cp.async.commit_group;" ::: "memory")
#define CP_WAIT1()     asm volatile("cp.async.wait_group 1;" ::: "memory")
#define CP_WAIT0()     asm volatile("cp.async.wait_group 0;" ::: "memory")

// quantize v (|v| <= M) to Q=qh*128+ql with scale M/16256
__device__ __forceinline__ void quant2(float v, float inv, signed char& qh,
                                       signed char& ql) {
    int Q = __float2int_rn(v * inv);         // |Q| <= 16256
    int h = (Q + 64) >> 7;                   // round(Q/128), h in [-127,127]
    qh = (signed char)h;
    ql = (signed char)(Q - (h << 7));        // in [-64,64]
}

// ============================================================
// K0: detect edge dtype
// ============================================================
__global__ void k_detect(const int* __restrict__ e) {
    const int t = threadIdx.x;
    int bad = 0;
    #pragma unroll
    for (int i = t; i < 256; i += 32) bad |= e[2 * i + 1];
    #pragma unroll
    for (int o = 16; o; o >>= 1) bad |= __shfl_xor_sync(0xffffffffu, bad, o);
    if (!t) g_is64 = (bad == 0) ? 1 : 0;
}

// ============================================================
// K1: transpose xs [B,C,N] -> xsT (fp32) + xsH (fp16)
// ============================================================
__global__ void k_transpose(const float* __restrict__ x) {
    __shared__ float tile[32][33];
    const int b  = blockIdx.z;
    const int n0 = blockIdx.x * 32;
    const int c0 = blockIdx.y * 32;
    const float* xb = x + (size_t)b * Cc * Nn;
    #pragma unroll
    for (int i = 0; i < 32; i += 8)
        tile[threadIdx.y + i][threadIdx.x] =
            xb[(size_t)(c0 + threadIdx.y + i) * Nn + n0 + threadIdx.x];
    __syncthreads();
    float*  xt  = g_xsT + (size_t)b * Nn * Cc;
    __half* xt2 = g_xsH + (size_t)b * Nn * Cc;
    #pragma unroll
    for (int i = 0; i < 32; i += 8) {
        const float v = tile[threadIdx.x][threadIdx.y + i];
        const size_t o = (size_t)(n0 + threadIdx.y + i) * Cc + c0 + threadIdx.x;
        xt[o]  = v;
        xt2[o] = __float2half_rn(v);
    }
}

// ============================================================
// K2: per-node attention pre-scores (one warp per node)
// ============================================================
__global__ void k_scores(const float* __restrict__ aw) {
    const int gw   = (blockIdx.x * blockDim.x + threadIdx.x) >> 5;
    const int lane = threadIdx.x & 31;
    if (gw >= BN_TOT) return;
    const float4* v  = (const float4*)(g_xsT + (size_t)gw * Cc);
    const float4* wi = (const float4*)aw;
    const float4* wj = (const float4*)(aw + Cc);
    float ai = 0.f, aj = 0.f;
    #pragma unroll
    for (int r = 0; r < 2; r++) {
        const int idx = lane + r * 32;
        float4 xv = v[idx], w1 = wi[idx], w2 = wj[idx];
        ai += xv.x * w1.x + xv.y * w1.y + xv.z * w1.z + xv.w * w1.w;
        aj += xv.x * w2.x + xv.y * w2.y + xv.z * w2.z + xv.w * w2.w;
    }
    #pragma unroll
    for (int o = 16; o; o >>= 1) {
        ai += __shfl_xor_sync(0xffffffffu, ai, o);
        aj += __shfl_xor_sync(0xffffffffu, aj, o);
    }
    if (!lane) { g_si[gw] = ai; g_sj[gw] = aj; }
}

// ============================================================
// K3: lane-per-edge softmax (16 lanes per node)
// ============================================================
__global__ __launch_bounds__(256) void k_softmax(const int* __restrict__ edge,
                                                 const float* __restrict__ ab) {
    const int gt = blockIdx.x * 256 + threadIdx.x;
    const int bn = gt >> 4;
    const int k  = gt & 15;
    const int sh = g_is64;
    const int b  = bn >> 11;
    const size_t ei = (size_t)(bn * Kk + k) << sh;
    const int i0 = edge[ei] & (Nn - 1);
    const int i1 = edge[(((size_t)BN_TOT * Kk) << sh) + ei] & (Nn - 1);
    const float e = g_si[b * Nn + i1] + g_sj[b * Nn + i0] + ab[0];
    float m = e;
    #pragma unroll
    for (int o = 8; o; o >>= 1) m = fmaxf(m, __shfl_xor_sync(0xffffffffu, m, o));
    const float ev = expf(e - m);
    float s = ev;
    #pragma unroll
    for (int o = 8; o; o >>= 1) s += __shfl_xor_sync(0xffffffffu, s, o);
    g_w[bn * Kk + k] = ev / s;
    g_j[bn * Kk + k] = i0;
}

// ============================================================
// K4: aggregation (fp16 gathers, fp32 accum) + interleave +
//     per-row max + int8 hi/lo quantization
// ============================================================
__global__ __launch_bounds__(256) void k_agg() {
    __shared__ float redmax[4][2];
    const int node = threadIdx.x >> 6;
    const int t    = threadIdx.x & 63;       // channel group c = 4t
    const int bn   = blockIdx.x * 4 + node;
    const int b    = bn >> 11;
    const uint2* base = (const uint2*)(g_xsH + (size_t)b * Nn * Cc);  // 64 uint2/row
    const int c = t * 4;
    const float4 xc = *(const float4*)(g_xsT + (size_t)bn * Cc + c);  // exact center
    float ax = 0.f, ay = 0.f, az = 0.f, aw_ = 0.f;
    const float* wp = g_w + bn * Kk;
    const int*   jp = g_j + bn * Kk;
    #pragma unroll
    for (int k = 0; k < Kk; k++) {
        const float wk = wp[k];
        const uint2 raw = base[(size_t)(jp[k] & (Nn - 1)) * 64 + t];
        const float2 p0 = __half22float2(*(const __half2*)&raw.x);
        const float2 p1 = __half22float2(*(const __half2*)&raw.y);
        ax += wk * p0.x; ay += wk * p0.y; az += wk * p1.x; aw_ += wk * p1.y;
    }
    const float v[8] = {xc.x, ax, xc.y, ay, xc.z, az, xc.w, aw_};
    // row max of |v| across the node's 64 threads (2 warps)
    float mx = 0.f;
    #pragma unroll
    for (int j = 0; j < 8; j++) mx = fmaxf(mx, fabsf(v[j]));
    #pragma unroll
    for (int o = 16; o; o >>= 1) mx = fmaxf(mx, __shfl_xor_sync(0xffffffffu, mx, o));
    if ((threadIdx.x & 31) == 0) redmax[node][(threadIdx.x >> 5) & 1] = mx;
    __syncthreads();
    float M = fmaxf(fmaxf(redmax[node][0], redmax[node][1]), 1e-20f);
    const float inv = 16256.f / M;
    union { uint2 u; signed char c[8]; } H, L;
    #pragma unroll
    for (int j = 0; j < 8; j++) quant2(v[j], inv, H.c[j], L.c[j]);
    const size_t o = (size_t)bn * KD + 8 * t;
    *(uint2*)(g_FQh + o) = H.u;
    *(uint2*)(g_FQl + o) = L.u;
    if (t == 0) g_sf[bn] = M * (1.f / 16256.f);
}

// ============================================================
// K4b: weight int8 hi/lo quantization, one warp per row
// ============================================================
__global__ void k_wq(const float* __restrict__ W) {
    const int row  = blockIdx.x * 8 + (threadIdx.x >> 5);
    const int lane = threadIdx.x & 31;
    const float* wp = W + (size_t)row * KD + lane * 16;
    float vals[16];
    float mx = 0.f;
    #pragma unroll
    for (int j = 0; j < 16; j++) { vals[j] = wp[j]; mx = fmaxf(mx, fabsf(vals[j])); }
    #pragma unroll
    for (int o = 16; o; o >>= 1) mx = fmaxf(mx, __shfl_xor_sync(0xffffffffu, mx, o));
    const float M   = fmaxf(mx, 1e-20f);
    const float inv = 16256.f / M;
    union { uint4 u; signed char c[16]; } H, L;
    #pragma unroll
    for (int j = 0; j < 16; j++) quant2(vals[j], inv, H.c[j], L.c[j]);
    const size_t o = (size_t)row * KD + lane * 16;
    *(uint4*)(g_WQh + o) = H.u;
    *(uint4*)(g_WQl + o) = L.u;
    if (!lane) g_sa[row] = M * (1.f / 16256.f);
}

// ============================================================
// K5: int8-split GEMM via mma.sync.m16n8k32.s8 (3 passes)
//     D = sa*sb*(16384*hh + 128*(hl+lh)); CTA 128x128, BK=32,
//     8 warps (64x32 warp tiles), cp.async double-buffered.
// ============================================================
#define PITCH8 48                 // byte pitch: 16B-aligned rows, bank-spread

__global__ __launch_bounds__(256, 1)
void k_gemm_i8(const float* __restrict__ bias, float* __restrict__ out) {
    __shared__ __align__(16) signed char sm[2][4][128][PITCH8];  // WH, WL, FH, FL

    const int tid  = threadIdx.x;
    const int lane = tid & 31;
    const int warp = tid >> 5;
    const int wm   = warp >> 2;     // 0..1
    const int wn   = warp & 3;      // 0..3
    const int nt   = blockIdx.x;
    const int mt   = blockIdx.y;

    const int lrow  = tid >> 1;
    const int lhalf = tid & 1;
    const signed char* pWH = g_WQh + (size_t)(mt * 128 + lrow) * KD + lhalf * 16;
    const signed char* pWL = g_WQl + (size_t)(mt * 128 + lrow) * KD + lhalf * 16;
    const signed char* pFH = g_FQh + (size_t)(nt * 128 + lrow) * KD + lhalf * 16;
    const signed char* pFL = g_FQl + (size_t)(nt * 128 + lrow) * KD + lhalf * 16;
    const uint32_t dWH = smem_u32(&sm[0][0][lrow][lhalf * 16]);
    const uint32_t dWL = smem_u32(&sm[0][1][lrow][lhalf * 16]);
    const uint32_t dFH = smem_u32(&sm[0][2][lrow][lhalf * 16]);
    const uint32_t dFL = smem_u32(&sm[0][3][lrow][lhalf * 16]);
    const uint32_t BUFB = 4 * 128 * PITCH8;    // 24576 bytes per buffer

    // prologue: stages 0 and 1 in flight (stage = K-chunk of 32 bytes)
    #pragma unroll
    for (int s = 0; s < 2; s++) {
        const int ko = s * 32;
        const uint32_t bo = s * BUFB;
        CP16(dWH + bo, pWH + ko);
        CP16(dWL + bo, pWL + ko);
        CP16(dFH + bo, pFH + ko);
        CP16(dFL + bo, pFL + ko);
        CP_COMMIT();
    }

    int acch[4][4][4], accm[4][4][4];
    #pragma unroll
    for (int i = 0; i < 4; i++)
        #pragma unroll
        for (int j = 0; j < 4; j++)
            #pragma unroll
            for (int q = 0; q < 4; q++) { acch[i][j][q] = 0; accm[i][j][q] = 0; }

    const int arow = wm * 64 + (lane & 7) + ((lane >> 3) & 1) * 8;   // + mf*16
    const int akb  = ((lane >> 4) & 1) * 16;                         // byte offset
    const int brow = wn * 32 + ((lane >> 4) & 1) * 8 + (lane & 7);   // + p*16
    const int bkb  = ((lane >> 3) & 1) * 16;

    #pragma unroll 1
    for (int kt = 0; kt < KD / 32; kt++) {       // 16 stages
        const int buf = kt & 1;
        if (kt < KD / 32 - 1) CP_WAIT1(); else CP_WAIT0();
        __syncthreads();

        uint32_t bqh[4][2], bql[4][2];
        #pragma unroll
        for (int p = 0; p < 2; p++) {
            uint32_t r[4];
            ldm4(r, smem_u32(&sm[buf][2][brow + p * 16][bkb]));
            bqh[2 * p][0] = r[0]; bqh[2 * p][1] = r[1];
            bqh[2 * p + 1][0] = r[2]; bqh[2 * p + 1][1] = r[3];
            ldm4(r, smem_u32(&sm[buf][3][brow + p * 16][bkb]));
            bql[2 * p][0] = r[0]; bql[2 * p][1] = r[1];
            bql[2 * p + 1][0] = r[2]; bql[2 * p + 1][1] = r[3];
        }
        #pragma unroll
        for (int mf = 0; mf < 4; mf++) {
            uint32_t ah[4], al[4];
            ldm4(ah, smem_u32(&sm[buf][0][arow + mf * 16][akb]));
            ldm4(al, smem_u32(&sm[buf][1][arow + mf * 16][akb]));
            #pragma unroll
            for (int nf = 0; nf < 4; nf++) {
                imma(acch[mf][nf], ah, bqh[nf]);   // hh
                imma(accm[mf][nf], ah, bql[nf]);   // hl
                imma(accm[mf][nf], al, bqh[nf]);   // lh
            }
        }
        __syncthreads();
        if (kt + 2 < KD / 32) {
            const int ko = (kt + 2) * 32;
            const uint32_t bo = buf * BUFB;
            CP16(dWH + bo, pWH + ko);
            CP16(dWL + bo, pWL + ko);
            CP16(dFH + bo, pFH + ko);
            CP16(dFL + bo, pFL + ko);
            CP_COMMIT();
        }
    }

    // epilogue: scale-combine + bias + relu
    const int g    = lane >> 2;
    const int tig  = lane & 3;
    const int bidx = nt >> 4;
    float sbv[4][2];
    #pragma unroll
    for (int nf = 0; nf < 4; nf++) {
        const int col = wn * 32 + 2 * tig + nf * 8;
        sbv[nf][0] = g_sf[nt * 128 + col];
        sbv[nf][1] = g_sf[nt * 128 + col + 1];
    }
    const int nb0 = (nt & 15) * 128 + wn * 32 + 2 * tig;
    #pragma unroll
    for (int mf = 0; mf < 4; mf++) {
        const int o0 = mt * 128 + wm * 64 + mf * 16 + g;
        const float sa0 = g_sa[o0], sa1 = g_sa[o0 + 8];
        const float b0  = bias[o0], b1  = bias[o0 + 8];
        float* r0 = out + ((size_t)(bidx * OUTd + o0) * Nn);
        float* r1 = out + ((size_t)(bidx * OUTd + o0 + 8) * Nn);
        #pragma unroll
        for (int nf = 0; nf < 4; nf++) {
            const int nb = nb0 + nf * 8;
            const float t0 = 16384.f * (float)acch[mf][nf][0] + 128.f * (float)accm[mf][nf][0];
            const float t1 = 16384.f * (float)acch[mf][nf][1] + 128.f * (float)accm[mf][nf][1];
            const float t2 = 16384.f * (float)acch[mf][nf][2] + 128.f * (float)accm[mf][nf][2];
            const float t3 = 16384.f * (float)acch[mf][nf][3] + 128.f * (float)accm[mf][nf][3];
            float2 w0, w1;
            w0.x = fmaxf(fmaf(t0, sa0 * sbv[nf][0], b0), 0.f);
            w0.y = fmaxf(fmaf(t1, sa0 * sbv[nf][1], b0), 0.f);
            w1.x = fmaxf(fmaf(t2, sa1 * sbv[nf][0], b1), 0.f);
            w1.y = fmaxf(fmaf(t3, sa1 * sbv[nf][1], b1), 0.f);
            *(float2*)(r0 + nb) = w0;
            *(float2*)(r1 + nb) = w1;
        }
    }
}

// ============================================================
// launch
// ============================================================
extern "C" void kernel_launch(void* const* d_in, const int* in_sizes, int n_in,
                              void* d_out, int out_size) {
    const float* x    = (const float*)d_in[0];
    const int*   edge = (const int*)d_in[1];
    const float* a_w  = (const float*)d_in[2];
    const float* a_b  = (const float*)d_in[3];
    const float* nn_w = (const float*)d_in[4];
    const float* nn_b = (const float*)d_in[5];
    float*       out  = (float*)d_out;

    k_detect   <<<1, 32>>>(edge);
    k_transpose<<<dim3(Nn / 32, Cc / 32, Bb), dim3(32, 8)>>>(x);
    k_scores   <<<(BN_TOT * 32) / 256, 256>>>(a_w);
    k_softmax  <<<(BN_TOT * Kk) / 256, 256>>>(edge, a_b);
    k_wq       <<<32, 256>>>(nn_w);
    k_agg      <<<BN_TOT / 4, 256>>>();
    k_gemm_i8  <<<dim3(NTILES, MTILES), 256>>>(nn_b, out);
}

// round 10
// speedup vs baseline: 2.2340x; 1.0754x over previous
#include <cuda_runtime.h>
#include <cuda_fp16.h>
#include <cstdint>

// Problem constants
#define Bb   8
#define Cc   256
#define Nn   2048
#define Kk   16
#define OUTd 256
#define KD   512                 // 2*C
#define BN_TOT (Bb*Nn)           // 16384
#define NT2  256                 // N tiles of 64
#define MTILES 2                 // 256/128

// ---- scratch (static device globals; no dynamic allocation) ----
__device__ float  g_xsT[BN_TOT * Cc];   // [B*N, C] fp32 node-major
__device__ __half g_xsH[BN_TOT * Cc];   // fp16 copy for neighbor gathers
__device__ float g_si [BN_TOT];
__device__ float g_sj [BN_TOT];
__device__ int   g_is64;

// int8 split operands (Q = qh*128 + ql, |Q| <= 16256), row-major [rows][512]
__device__ signed char g_FQh[(size_t)BN_TOT * KD];
__device__ signed char g_FQl[(size_t)BN_TOT * KD];
__device__ signed char g_WQh[(size_t)OUTd * KD];
__device__ signed char g_WQl[(size_t)OUTd * KD];
__device__ float g_sf[BN_TOT];          // per-feature-row scale
__device__ float g_sa[OUTd];            // per-weight-row scale

// ============================================================
// helpers
// ============================================================
__device__ __forceinline__ uint32_t smem_u32(const void* p) {
    uint32_t a;
    asm("{ .reg .u64 t; cvta.to.shared.u64 t, %1; cvt.u32.u64 %0, t; }"
        : "=r"(a) : "l"(p));
    return a;
}
__device__ __forceinline__ void ldm4(uint32_t* r, uint32_t addr) {
    asm volatile("ldmatrix.sync.aligned.m8n8.x4.shared.b16 {%0,%1,%2,%3}, [%4];"
                 : "=r"(r[0]), "=r"(r[1]), "=r"(r[2]), "=r"(r[3]) : "r"(addr));
}
__device__ __forceinline__ void imma(int* d, const uint32_t* a, const uint32_t* b) {
    asm volatile(
        "mma.sync.aligned.m16n8k32.row.col.s32.s8.s8.s32 "
        "{%0,%1,%2,%3}, {%4,%5,%6,%7}, {%8,%9}, {%0,%1,%2,%3};"
        : "+r"(d[0]), "+r"(d[1]), "+r"(d[2]), "+r"(d[3])
        : "r"(a[0]), "r"(a[1]), "r"(a[2]), "r"(a[3]), "r"(b[0]), "r"(b[1]));
}
#define CP16(dst, src) asm volatile("cp.async.cg.shared.global [%0], [%1], 16;" :: "r"(dst), "l"(src))
#define CP_COMMIT()    asm volatile("cp.async.commit_group;" ::: "memory")
#define CP_WAIT1()     asm volatile("cp.async.wait_group 1;" ::: "memory")
#define CP_WAIT0()     asm volatile("cp.async.wait_group 0;" ::: "memory")

__device__ __forceinline__ void quant2(float v, float inv, signed char& qh,
                                       signed char& ql) {
    int Q = __float2int_rn(v * inv);         // |Q| <= 16256
    int h = (Q + 64) >> 7;                   // round(Q/128)
    qh = (signed char)h;
    ql = (signed char)(Q - (h << 7));        // in [-64,64]
}

// ============================================================
// K0: detect edge dtype
// ============================================================
__global__ void k_detect(const int* __restrict__ e) {
    const int t = threadIdx.x;
    int bad = 0;
    #pragma unroll
    for (int i = t; i < 256; i += 32) bad |= e[2 * i + 1];
    #pragma unroll
    for (int o = 16; o; o >>= 1) bad |= __shfl_xor_sync(0xffffffffu, bad, o);
    if (!t) g_is64 = (bad == 0) ? 1 : 0;
}

// ============================================================
// K1: transpose xs [B,C,N] -> xsT (fp32) + xsH (fp16)
// ============================================================
__global__ void k_transpose(const float* __restrict__ x) {
    __shared__ float tile[32][33];
    const int b  = blockIdx.z;
    const int n0 = blockIdx.x * 32;
    const int c0 = blockIdx.y * 32;
    const float* xb = x + (size_t)b * Cc * Nn;
    #pragma unroll
    for (int i = 0; i < 32; i += 8)
        tile[threadIdx.y + i][threadIdx.x] =
            xb[(size_t)(c0 + threadIdx.y + i) * Nn + n0 + threadIdx.x];
    __syncthreads();
    float*  xt  = g_xsT + (size_t)b * Nn * Cc;
    __half* xt2 = g_xsH + (size_t)b * Nn * Cc;
    #pragma unroll
    for (int i = 0; i < 32; i += 8) {
        const float v = tile[threadIdx.x][threadIdx.y + i];
        const size_t o = (size_t)(n0 + threadIdx.y + i) * Cc + c0 + threadIdx.x;
        xt[o]  = v;
        xt2[o] = __float2half_rn(v);
    }
}

// ============================================================
// K2: per-node attention pre-scores (one warp per node)
// ============================================================
__global__ void k_scores(const float* __restrict__ aw) {
    const int gw   = (blockIdx.x * blockDim.x + threadIdx.x) >> 5;
    const int lane = threadIdx.x & 31;
    if (gw >= BN_TOT) return;
    const float4* v  = (const float4*)(g_xsT + (size_t)gw * Cc);
    const float4* wi = (const float4*)aw;
    const float4* wj = (const float4*)(aw + Cc);
    float ai = 0.f, aj = 0.f;
    #pragma unroll
    for (int r = 0; r < 2; r++) {
        const int idx = lane + r * 32;
        float4 xv = v[idx], w1 = wi[idx], w2 = wj[idx];
        ai += xv.x * w1.x + xv.y * w1.y + xv.z * w1.z + xv.w * w1.w;
        aj += xv.x * w2.x + xv.y * w2.y + xv.z * w2.z + xv.w * w2.w;
    }
    #pragma unroll
    for (int o = 16; o; o >>= 1) {
        ai += __shfl_xor_sync(0xffffffffu, ai, o);
        aj += __shfl_xor_sync(0xffffffffu, aj, o);
    }
    if (!lane) { g_si[gw] = ai; g_sj[gw] = aj; }
}

// ============================================================
// K4: FUSED softmax + aggregation + int8 quantization.
//     4 nodes/block, 64 threads/node. Lanes 0..15 of each node's
//     first warp compute the 16-way softmax; smem broadcast.
// ============================================================
__global__ __launch_bounds__(256) void k_agg(const int* __restrict__ edge,
                                             const float* __restrict__ ab) {
    __shared__ float sw[4][16];
    __shared__ int   sjj[4][16];
    __shared__ float redmax[4][2];
    const int node = threadIdx.x >> 6;
    const int t    = threadIdx.x & 63;
    const int bn   = blockIdx.x * 4 + node;
    const int b    = bn >> 11;

    // --- softmax (lanes 0..15 of each node's first warp) ---
    if (t < 16) {
        const int sh = g_is64;
        const size_t ei = (size_t)(bn * Kk + t) << sh;
        const int i0 = edge[ei] & (Nn - 1);
        const int i1 = edge[(((size_t)BN_TOT * Kk) << sh) + ei] & (Nn - 1);
        const float e = g_si[b * Nn + i1] + g_sj[b * Nn + i0] + ab[0];
        float m = e;
        #pragma unroll
        for (int o = 8; o; o >>= 1) m = fmaxf(m, __shfl_xor_sync(0xffffu, m, o));
        const float ev = expf(e - m);
        float s = ev;
        #pragma unroll
        for (int o = 8; o; o >>= 1) s += __shfl_xor_sync(0xffffu, s, o);
        sw[node][t]  = ev / s;
        sjj[node][t] = i0;
    }
    __syncthreads();

    // --- aggregation (fp16 gathers, fp32 accum) ---
    const uint2* base = (const uint2*)(g_xsH + (size_t)b * Nn * Cc);  // 64 uint2/row
    const int c = t * 4;
    const float4 xc = *(const float4*)(g_xsT + (size_t)bn * Cc + c);  // exact center
    float ax = 0.f, ay = 0.f, az = 0.f, aw_ = 0.f;
    #pragma unroll
    for (int k = 0; k < Kk; k++) {
        const float wk = sw[node][k];
        const uint2 raw = base[(size_t)sjj[node][k] * 64 + t];
        const float2 p0 = __half22float2(*(const __half2*)&raw.x);
        const float2 p1 = __half22float2(*(const __half2*)&raw.y);
        ax += wk * p0.x; ay += wk * p0.y; az += wk * p1.x; aw_ += wk * p1.y;
    }
    const float v[8] = {xc.x, ax, xc.y, ay, xc.z, az, xc.w, aw_};

    // --- row max + int8 hi/lo quantization ---
    float mx = 0.f;
    #pragma unroll
    for (int j = 0; j < 8; j++) mx = fmaxf(mx, fabsf(v[j]));
    #pragma unroll
    for (int o = 16; o; o >>= 1) mx = fmaxf(mx, __shfl_xor_sync(0xffffffffu, mx, o));
    if ((threadIdx.x & 31) == 0) redmax[node][(threadIdx.x >> 5) & 1] = mx;
    __syncthreads();
    const float M   = fmaxf(fmaxf(redmax[node][0], redmax[node][1]), 1e-20f);
    const float inv = 16256.f / M;
    union { uint2 u; signed char ch[8]; } H, L;
    #pragma unroll
    for (int j = 0; j < 8; j++) quant2(v[j], inv, H.ch[j], L.ch[j]);
    const size_t o = (size_t)bn * KD + 8 * t;
    *(uint2*)(g_FQh + o) = H.u;
    *(uint2*)(g_FQl + o) = L.u;
    if (t == 0) g_sf[bn] = M * (1.f / 16256.f);
}

// ============================================================
// K4b: weight int8 hi/lo quantization, one warp per row
// ============================================================
__global__ void k_wq(const float* __restrict__ W) {
    const int row  = blockIdx.x * 8 + (threadIdx.x >> 5);
    const int lane = threadIdx.x & 31;
    const float* wp = W + (size_t)row * KD + lane * 16;
    float vals[16];
    float mx = 0.f;
    #pragma unroll
    for (int j = 0; j < 16; j++) { vals[j] = wp[j]; mx = fmaxf(mx, fabsf(vals[j])); }
    #pragma unroll
    for (int o = 16; o; o >>= 1) mx = fmaxf(mx, __shfl_xor_sync(0xffffffffu, mx, o));
    const float M   = fmaxf(mx, 1e-20f);
    const float inv = 16256.f / M;
    union { uint4 u; signed char c[16]; } H, L;
    #pragma unroll
    for (int j = 0; j < 16; j++) quant2(vals[j], inv, H.c[j], L.c[j]);
    const size_t o = (size_t)row * KD + lane * 16;
    *(uint4*)(g_WQh + o) = H.u;
    *(uint4*)(g_WQl + o) = L.u;
    if (!lane) g_sa[row] = M * (1.f / 16256.f);
}

// ============================================================
// K5: int8-split GEMM, CTA 128(M)x64(N), 2 CTAs/SM.
//     8 warps, 32x32 warp tiles. cp.async double-buffered.
//     smem rows: [0,128) WH | [128,256) WL | [256,320) FH | [320,384) FL
// ============================================================
#define PITCH8 48
#define SROWS  384
#define BUFB   (SROWS * PITCH8)   // 18432 bytes

__global__ __launch_bounds__(256, 2)
void k_gemm_i8(const float* __restrict__ bias, float* __restrict__ out) {
    __shared__ __align__(16) signed char sm[2][SROWS][PITCH8];

    const int tid  = threadIdx.x;
    const int lane = tid & 31;
    const int warp = tid >> 5;
    const int wm   = warp >> 1;     // 0..3  (m offset wm*32)
    const int wn   = warp & 1;      // 0..1  (n offset wn*32)
    const int nt   = blockIdx.x;    // 0..255 (64-col tiles)
    const int mt   = blockIdx.y;    // 0..1

    const int lrow  = tid >> 1;
    const int lhalf = tid & 1;
    const signed char* pWH = g_WQh + (size_t)(mt * 128 + lrow) * KD + lhalf * 16;
    const signed char* pWL = g_WQl + (size_t)(mt * 128 + lrow) * KD + lhalf * 16;
    const signed char* pFH = g_FQh + (size_t)(nt * 64 + (lrow & 63)) * KD + lhalf * 16;
    const signed char* pFL = g_FQl + (size_t)(nt * 64 + (lrow & 63)) * KD + lhalf * 16;
    const uint32_t dWH = smem_u32(&sm[0][lrow][lhalf * 16]);
    const uint32_t dWL = smem_u32(&sm[0][128 + lrow][lhalf * 16]);
    const uint32_t dFH = smem_u32(&sm[0][256 + (lrow & 63)][lhalf * 16]);
    const uint32_t dFL = smem_u32(&sm[0][320 + (lrow & 63)][lhalf * 16]);
    const bool doF = (tid < 128);

    #pragma unroll
    for (int s = 0; s < 2; s++) {
        const int ko = s * 32;
        const uint32_t bo = s * BUFB;
        CP16(dWH + bo, pWH + ko);
        CP16(dWL + bo, pWL + ko);
        if (doF) { CP16(dFH + bo, pFH + ko); CP16(dFL + bo, pFL + ko); }
        CP_COMMIT();
    }

    int acch[2][4][4], accm[2][4][4];
    #pragma unroll
    for (int i = 0; i < 2; i++)
        #pragma unroll
        for (int j = 0; j < 4; j++)
            #pragma unroll
            for (int q = 0; q < 4; q++) { acch[i][j][q] = 0; accm[i][j][q] = 0; }

    const int arow = wm * 32 + (lane & 7) + ((lane >> 3) & 1) * 8;   // + mf*16
    const int akb  = ((lane >> 4) & 1) * 16;
    const int brow = wn * 32 + ((lane >> 4) & 1) * 8 + (lane & 7);   // + p*16
    const int bkb  = ((lane >> 3) & 1) * 16;

    #pragma unroll 1
    for (int kt = 0; kt < KD / 32; kt++) {
        const int buf = kt & 1;
        if (kt < KD / 32 - 1) CP_WAIT1(); else CP_WAIT0();
        __syncthreads();

        uint32_t bqh[4][2], bql[4][2];
        #pragma unroll
        for (int p = 0; p < 2; p++) {
            uint32_t r[4];
            ldm4(r, smem_u32(&sm[buf][256 + brow + p * 16][bkb]));
            bqh[2 * p][0] = r[0]; bqh[2 * p][1] = r[1];
            bqh[2 * p + 1][0] = r[2]; bqh[2 * p + 1][1] = r[3];
            ldm4(r, smem_u32(&sm[buf][320 + brow + p * 16][bkb]));
            bql[2 * p][0] = r[0]; bql[2 * p][1] = r[1];
            bql[2 * p + 1][0] = r[2]; bql[2 * p + 1][1] = r[3];
        }
        #pragma unroll
        for (int mf = 0; mf < 2; mf++) {
            uint32_t ah[4], al[4];
            ldm4(ah, smem_u32(&sm[buf][arow + mf * 16][akb]));
            ldm4(al, smem_u32(&sm[buf][128 + arow + mf * 16][akb]));
            #pragma unroll
            for (int nf = 0; nf < 4; nf++) {
                imma(acch[mf][nf], ah, bqh[nf]);   // hh
                imma(accm[mf][nf], ah, bql[nf]);   // hl
                imma(accm[mf][nf], al, bqh[nf]);   // lh
            }
        }
        __syncthreads();
        if (kt + 2 < KD / 32) {
            const int ko = (kt + 2) * 32;
            const uint32_t bo = buf * BUFB;
            CP16(dWH + bo, pWH + ko);
            CP16(dWL + bo, pWL + ko);
            if (doF) { CP16(dFH + bo, pFH + ko); CP16(dFL + bo, pFL + ko); }
            CP_COMMIT();
        }
    }

    // epilogue: scale-combine + bias + relu
    const int g    = lane >> 2;
    const int tig  = lane & 3;
    const int bidx = nt >> 5;                  // 2048/64 = 32 tiles per batch
    float sbv[4][2];
    #pragma unroll
    for (int nf = 0; nf < 4; nf++) {
        const int col = nt * 64 + wn * 32 + 2 * tig + nf * 8;
        sbv[nf][0] = g_sf[col];
        sbv[nf][1] = g_sf[col + 1];
    }
    const int nb0 = (nt & 31) * 64 + wn * 32 + 2 * tig;
    #pragma unroll
    for (int mf = 0; mf < 2; mf++) {
        const int o0 = mt * 128 + wm * 32 + mf * 16 + g;
        const float sa0 = g_sa[o0], sa1 = g_sa[o0 + 8];
        const float b0  = bias[o0], b1  = bias[o0 + 8];
        float* r0 = out + ((size_t)(bidx * OUTd + o0) * Nn);
        float* r1 = out + ((size_t)(bidx * OUTd + o0 + 8) * Nn);
        #pragma unroll
        for (int nf = 0; nf < 4; nf++) {
            const int nb = nb0 + nf * 8;
            const float t0 = 16384.f * (float)acch[mf][nf][0] + 128.f * (float)accm[mf][nf][0];
            const float t1 = 16384.f * (float)acch[mf][nf][1] + 128.f * (float)accm[mf][nf][1];
            const float t2 = 16384.f * (float)acch[mf][nf][2] + 128.f * (float)accm[mf][nf][2];
            const float t3 = 16384.f * (float)acch[mf][nf][3] + 128.f * (float)accm[mf][nf][3];
            float2 w0, w1;
            w0.x = fmaxf(fmaf(t0, sa0 * sbv[nf][0], b0), 0.f);
            w0.y = fmaxf(fmaf(t1, sa0 * sbv[nf][1], b0), 0.f);
            w1.x = fmaxf(fmaf(t2, sa1 * sbv[nf][0], b1), 0.f);
            w1.y = fmaxf(fmaf(t3, sa1 * sbv[nf][1], b1), 0.f);
            *(float2*)(r0 + nb) = w0;
            *(float2*)(r1 + nb) = w1;
        }
    }
}

// ============================================================
// launch
// ============================================================
extern "C" void kernel_launch(void* const* d_in, const int* in_sizes, int n_in,
                              void* d_out, int out_size) {
    const float* x    = (const float*)d_in[0];
    const int*   edge = (const int*)d_in[1];
    const float* a_w  = (const float*)d_in[2];
    const float* a_b  = (const float*)d_in[3];
    const float* nn_w = (const float*)d_in[4];
    const float* nn_b = (const float*)d_in[5];
    float*       out  = (float*)d_out;

    k_detect   <<<1, 32>>>(edge);
    k_transpose<<<dim3(Nn / 32, Cc / 32, Bb), dim3(32, 8)>>>(x);
    k_scores   <<<(BN_TOT * 32) / 256, 256>>>(a_w);
    k_wq       <<<32, 256>>>(nn_w);
    k_agg      <<<BN_TOT / 4, 256>>>(edge, a_b);
    k_gemm_i8  <<<dim3(NT2, MTILES), 256>>>(nn_b, out);
}

// round 12
// speedup vs baseline: 2.4308x; 1.0881x over previous
#include <cuda_runtime.h>
#include <cuda_fp16.h>
#include <cstdint>

// Problem constants
#define Bb   8
#define Cc   256
#define Nn   2048
#define Kk   16
#define OUTd 256
#define KD   512                 // 2*C
#define BN_TOT (Bb*Nn)           // 16384
#define NT2  256                 // N tiles of 64
#define MTILES 2                 // 256/128

// ---- scratch (static device globals; no dynamic allocation) ----
__device__ __half g_xsH[BN_TOT * Cc];   // fp16 node-major features
__device__ float g_si [BN_TOT];
__device__ float g_sj [BN_TOT];
__device__ int   g_is64;

// int8 split operands (Q = qh*128 + ql, |Q| <= 16256), row-major [rows][512]
__device__ signed char g_FQh[(size_t)BN_TOT * KD];
__device__ signed char g_FQl[(size_t)BN_TOT * KD];
__device__ signed char g_WQh[(size_t)OUTd * KD];
__device__ signed char g_WQl[(size_t)OUTd * KD];
__device__ float g_sf[BN_TOT];          // per-feature-row scale
__device__ float g_sa[OUTd];            // per-weight-row scale

// ============================================================
// helpers
// ============================================================
__device__ __forceinline__ uint32_t smem_u32(const void* p) {
    uint32_t a;
    asm("{ .reg .u64 t; cvta.to.shared.u64 t, %1; cvt.u32.u64 %0, t; }"
        : "=r"(a) : "l"(p));
    return a;
}
__device__ __forceinline__ void ldm4(uint32_t* r, uint32_t addr) {
    asm volatile("ldmatrix.sync.aligned.m8n8.x4.shared.b16 {%0,%1,%2,%3}, [%4];"
                 : "=r"(r[0]), "=r"(r[1]), "=r"(r[2]), "=r"(r[3]) : "r"(addr));
}
__device__ __forceinline__ void imma(int* d, const uint32_t* a, const uint32_t* b) {
    asm volatile(
        "mma.sync.aligned.m16n8k32.row.col.s32.s8.s8.s32 "
        "{%0,%1,%2,%3}, {%4,%5,%6,%7}, {%8,%9}, {%0,%1,%2,%3};"
        : "+r"(d[0]), "+r"(d[1]), "+r"(d[2]), "+r"(d[3])
        : "r"(a[0]), "r"(a[1]), "r"(a[2]), "r"(a[3]), "r"(b[0]), "r"(b[1]));
}
#define CP16(dst, src) asm volatile("cp.async.cg.shared.global [%0], [%1], 16;" :: "r"(dst), "l"(src))
#define CP_COMMIT()    asm volatile("cp.async.commit_group;" ::: "memory")
#define CP_WAIT1()     asm volatile("cp.async.wait_group 1;" ::: "memory")
#define CP_WAIT0()     asm volatile("cp.async.wait_group 0;" ::: "memory")

__device__ __forceinline__ void quant2(float v, float inv, signed char& qh,
                                       signed char& ql) {
    int Q = __float2int_rn(v * inv);         // |Q| <= 16256
    int h = (Q + 64) >> 7;                   // round(Q/128)
    qh = (signed char)h;
    ql = (signed char)(Q - (h << 7));        // in [-64,64]
}

// ============================================================
// K0: weight int8 hi/lo quantization (one block = one row) +
//     edge-dtype detection in block 0.
// ============================================================
__global__ void k_wq(const float* __restrict__ W, const int* __restrict__ e) {
    const int lane = threadIdx.x;            // 32 threads
    if (blockIdx.x == 0) {
        int bad = 0;
        #pragma unroll
        for (int i = lane; i < 256; i += 32) bad |= e[2 * i + 1];
        #pragma unroll
        for (int o = 16; o; o >>= 1) bad |= __shfl_xor_sync(0xffffffffu, bad, o);
        if (!lane) g_is64 = (bad == 0) ? 1 : 0;
    }
    const int row = blockIdx.x;
    const float* wp = W + (size_t)row * KD + lane * 16;
    float vals[16];
    float mx = 0.f;
    #pragma unroll
    for (int j = 0; j < 16; j++) { vals[j] = wp[j]; mx = fmaxf(mx, fabsf(vals[j])); }
    #pragma unroll
    for (int o = 16; o; o >>= 1) mx = fmaxf(mx, __shfl_xor_sync(0xffffffffu, mx, o));
    const float M   = fmaxf(mx, 1e-20f);
    const float inv = 16256.f / M;
    union { uint4 u; signed char c[16]; } H, L;
    #pragma unroll
    for (int j = 0; j < 16; j++) quant2(vals[j], inv, H.c[j], L.c[j]);
    const size_t o = (size_t)row * KD + lane * 16;
    *(uint4*)(g_WQh + o) = H.u;
    *(uint4*)(g_WQl + o) = L.u;
    if (!lane) g_sa[row] = M * (1.f / 16256.f);
}

// ============================================================
// K1: transpose xs [B,C,N] -> xsH [B*N, C] (fp16)
// ============================================================
__global__ void k_transpose(const float* __restrict__ x) {
    __shared__ float tile[32][33];
    const int b  = blockIdx.z;
    const int n0 = blockIdx.x * 32;
    const int c0 = blockIdx.y * 32;
    const float* xb = x + (size_t)b * Cc * Nn;
    #pragma unroll
    for (int i = 0; i < 32; i += 8)
        tile[threadIdx.y + i][threadIdx.x] =
            xb[(size_t)(c0 + threadIdx.y + i) * Nn + n0 + threadIdx.x];
    __syncthreads();
    __half* xt = g_xsH + (size_t)b * Nn * Cc;
    #pragma unroll
    for (int i = 0; i < 32; i += 8) {
        const float v = tile[threadIdx.x][threadIdx.y + i];
        xt[(size_t)(n0 + threadIdx.y + i) * Cc + c0 + threadIdx.x] = __float2half_rn(v);
    }
}

// ============================================================
// K2: per-node attention pre-scores from fp16 (one warp per node)
// ============================================================
__global__ void k_scores(const float* __restrict__ aw) {
    const int gw   = (blockIdx.x * blockDim.x + threadIdx.x) >> 5;
    const int lane = threadIdx.x & 31;
    if (gw >= BN_TOT) return;
    const uint4*  v  = (const uint4*)(g_xsH + (size_t)gw * Cc);   // 32 uint4 (8 halfs)
    const float4* wi = (const float4*)aw;
    const float4* wj = (const float4*)(aw + Cc);
    const uint4 xv = v[lane];
    const float2 p0 = __half22float2(*(const __half2*)&xv.x);
    const float2 p1 = __half22float2(*(const __half2*)&xv.y);
    const float2 p2 = __half22float2(*(const __half2*)&xv.z);
    const float2 p3 = __half22float2(*(const __half2*)&xv.w);
    const float xf[8] = {p0.x, p0.y, p1.x, p1.y, p2.x, p2.y, p3.x, p3.y};
    const float4 w1a = wi[2 * lane], w1b = wi[2 * lane + 1];
    const float4 w2a = wj[2 * lane], w2b = wj[2 * lane + 1];
    const float w1[8] = {w1a.x, w1a.y, w1a.z, w1a.w, w1b.x, w1b.y, w1b.z, w1b.w};
    const float w2[8] = {w2a.x, w2a.y, w2a.z, w2a.w, w2b.x, w2b.y, w2b.z, w2b.w};
    float ai = 0.f, aj = 0.f;
    #pragma unroll
    for (int j = 0; j < 8; j++) { ai += xf[j] * w1[j]; aj += xf[j] * w2[j]; }
    #pragma unroll
    for (int o = 16; o; o >>= 1) {
        ai += __shfl_xor_sync(0xffffffffu, ai, o);
        aj += __shfl_xor_sync(0xffffffffu, aj, o);
    }
    if (!lane) { g_si[gw] = ai; g_sj[gw] = aj; }
}

// ============================================================
// K4: FUSED softmax + aggregation + int8 quantization.
//     4 nodes/block, 64 threads/node; fp16 gathers + fp16 center.
// ============================================================
__global__ __launch_bounds__(256) void k_agg(const int* __restrict__ edge,
                                             const float* __restrict__ ab) {
    __shared__ float sw[4][16];
    __shared__ int   sjj[4][16];
    __shared__ float redmax[4][2];
    const int node = threadIdx.x >> 6;
    const int t    = threadIdx.x & 63;
    const int bn   = blockIdx.x * 4 + node;
    const int b    = bn >> 11;

    // --- softmax (lanes 0..15 of each node's first warp) ---
    if (t < 16) {
        const int sh = g_is64;
        const size_t ei = (size_t)(bn * Kk + t) << sh;
        const int i0 = edge[ei] & (Nn - 1);
        const int i1 = edge[(((size_t)BN_TOT * Kk) << sh) + ei] & (Nn - 1);
        const float e = g_si[b * Nn + i1] + g_sj[b * Nn + i0] + ab[0];
        float m = e;
        #pragma unroll
        for (int o = 8; o; o >>= 1) m = fmaxf(m, __shfl_xor_sync(0xffffu, m, o));
        const float ev = expf(e - m);
        float s = ev;
        #pragma unroll
        for (int o = 8; o; o >>= 1) s += __shfl_xor_sync(0xffffu, s, o);
        sw[node][t]  = ev / s;
        sjj[node][t] = i0;
    }
    __syncthreads();

    // --- aggregation (fp16 gathers, fp32 accum) ---
    const uint2* base = (const uint2*)(g_xsH + (size_t)b * Nn * Cc);  // 64 uint2/row
    const uint2 craw = base[(size_t)(bn & (Nn - 1)) * 64 + t];        // center (fp16)
    const float2 c0 = __half22float2(*(const __half2*)&craw.x);
    const float2 c1 = __half22float2(*(const __half2*)&craw.y);
    float ax = 0.f, ay = 0.f, az = 0.f, aw_ = 0.f;
    #pragma unroll
    for (int k = 0; k < Kk; k++) {
        const float wk = sw[node][k];
        const uint2 raw = base[(size_t)sjj[node][k] * 64 + t];
        const float2 p0 = __half22float2(*(const __half2*)&raw.x);
        const float2 p1 = __half22float2(*(const __half2*)&raw.y);
        ax += wk * p0.x; ay += wk * p0.y; az += wk * p1.x; aw_ += wk * p1.y;
    }
    const float v[8] = {c0.x, ax, c0.y, ay, c1.x, az, c1.y, aw_};

    // --- row max + int8 hi/lo quantization ---
    float mx = 0.f;
    #pragma unroll
    for (int j = 0; j < 8; j++) mx = fmaxf(mx, fabsf(v[j]));
    #pragma unroll
    for (int o = 16; o; o >>= 1) mx = fmaxf(mx, __shfl_xor_sync(0xffffffffu, mx, o));
    if ((threadIdx.x & 31) == 0) redmax[node][(threadIdx.x >> 5) & 1] = mx;
    __syncthreads();
    const float M   = fmaxf(fmaxf(redmax[node][0], redmax[node][1]), 1e-20f);
    const float inv = 16256.f / M;
    union { uint2 u; signed char ch[8]; } H, L;
    #pragma unroll
    for (int j = 0; j < 8; j++) quant2(v[j], inv, H.ch[j], L.ch[j]);
    const size_t o = (size_t)bn * KD + 8 * t;
    *(uint2*)(g_FQh + o) = H.u;
    *(uint2*)(g_FQl + o) = L.u;
    if (t == 0) g_sf[bn] = M * (1.f / 16256.f);
}

// ============================================================
// K5: int8-split GEMM, CTA 128(M)x64(N), 2 CTAs/SM.
//     8 warps, 32x32 warp tiles. cp.async double-buffered.
//     smem rows: [0,128) WH | [128,256) WL | [256,320) FH | [320,384) FL
// ============================================================
#define PITCH8 48
#define SROWS  384
#define BUFB   (SROWS * PITCH8)   // 18432 bytes

__global__ __launch_bounds__(256, 2)
void k_gemm_i8(const float* __restrict__ bias, float* __restrict__ out) {
    __shared__ __align__(16) signed char sm[2][SROWS][PITCH8];

    const int tid  = threadIdx.x;
    const int lane = tid & 31;
    const int warp = tid >> 5;
    const int wm   = warp >> 1;     // 0..3  (m offset wm*32)
    const int wn   = warp & 1;      // 0..1  (n offset wn*32)
    const int nt   = blockIdx.x;    // 0..255 (64-col tiles)
    const int mt   = blockIdx.y;    // 0..1

    const int lrow  = tid >> 1;
    const int lhalf = tid & 1;
    const signed char* pWH = g_WQh + (size_t)(mt * 128 + lrow) * KD + lhalf * 16;
    const signed char* pWL = g_WQl + (size_t)(mt * 128 + lrow) * KD + lhalf * 16;
    const signed char* pFH = g_FQh + (size_t)(nt * 64 + (lrow & 63)) * KD + lhalf * 16;
    const signed char* pFL = g_FQl + (size_t)(nt * 64 + (lrow & 63)) * KD + lhalf * 16;
    const uint32_t dWH = smem_u32(&sm[0][lrow][lhalf * 16]);
    const uint32_t dWL = smem_u32(&sm[0][128 + lrow][lhalf * 16]);
    const uint32_t dFH = smem_u32(&sm[0][256 + (lrow & 63)][lhalf * 16]);
    const uint32_t dFL = smem_u32(&sm[0][320 + (lrow & 63)][lhalf * 16]);
    const bool doF = (tid < 128);

    #pragma unroll
    for (int s = 0; s < 2; s++) {
        const int ko = s * 32;
        const uint32_t bo = s * BUFB;
        CP16(dWH + bo, pWH + ko);
        CP16(dWL + bo, pWL + ko);
        if (doF) { CP16(dFH + bo, pFH + ko); CP16(dFL + bo, pFL + ko); }
        CP_COMMIT();
    }

    int acch[2][4][4], accm[2][4][4];
    #pragma unroll
    for (int i = 0; i < 2; i++)
        #pragma unroll
        for (int j = 0; j < 4; j++)
            #pragma unroll
            for (int q = 0; q < 4; q++) { acch[i][j][q] = 0; accm[i][j][q] = 0; }

    const int arow = wm * 32 + (lane & 7) + ((lane >> 3) & 1) * 8;   // + mf*16
    const int akb  = ((lane >> 4) & 1) * 16;
    const int brow = wn * 32 + ((lane >> 4) & 1) * 8 + (lane & 7);   // + p*16
    const int bkb  = ((lane >> 3) & 1) * 16;

    #pragma unroll 1
    for (int kt = 0; kt < KD / 32; kt++) {
        const int buf = kt & 1;
        if (kt < KD / 32 - 1) CP_WAIT1(); else CP_WAIT0();
        __syncthreads();

        uint32_t bqh[4][2], bql[4][2];
        #pragma unroll
        for (int p = 0; p < 2; p++) {
            uint32_t r[4];
            ldm4(r, smem_u32(&sm[buf][256 + brow + p * 16][bkb]));
            bqh[2 * p][0] = r[0]; bqh[2 * p][1] = r[1];
            bqh[2 * p + 1][0] = r[2]; bqh[2 * p + 1][1] = r[3];
            ldm4(r, smem_u32(&sm[buf][320 + brow + p * 16][bkb]));
            bql[2 * p][0] = r[0]; bql[2 * p][1] = r[1];
            bql[2 * p + 1][0] = r[2]; bql[2 * p + 1][1] = r[3];
        }
        #pragma unroll
        for (int mf = 0; mf < 2; mf++) {
            uint32_t ah[4], al[4];
            ldm4(ah, smem_u32(&sm[buf][arow + mf * 16][akb]));
            ldm4(al, smem_u32(&sm[buf][128 + arow + mf * 16][akb]));
            #pragma unroll
            for (int nf = 0; nf < 4; nf++) {
                imma(acch[mf][nf], ah, bqh[nf]);   // hh
                imma(accm[mf][nf], ah, bql[nf]);   // hl
                imma(accm[mf][nf], al, bqh[nf]);   // lh
            }
        }
        __syncthreads();
        if (kt + 2 < KD / 32) {
            const int ko = (kt + 2) * 32;
            const uint32_t bo = buf * BUFB;
            CP16(dWH + bo, pWH + ko);
            CP16(dWL + bo, pWL + ko);
            if (doF) { CP16(dFH + bo, pFH + ko); CP16(dFL + bo, pFL + ko); }
            CP_COMMIT();
        }
    }

    // epilogue: scale-combine + bias + relu
    const int g    = lane >> 2;
    const int tig  = lane & 3;
    const int bidx = nt >> 5;                  // 32 tiles per batch
    float sbv[4][2];
    #pragma unroll
    for (int nf = 0; nf < 4; nf++) {
        const int col = nt * 64 + wn * 32 + 2 * tig + nf * 8;
        sbv[nf][0] = g_sf[col];
        sbv[nf][1] = g_sf[col + 1];
    }
    const int nb0 = (nt & 31) * 64 + wn * 32 + 2 * tig;
    #pragma unroll
    for (int mf = 0; mf < 2; mf++) {
        const int o0 = mt * 128 + wm * 32 + mf * 16 + g;
        const float sa0 = g_sa[o0], sa1 = g_sa[o0 + 8];
        const float b0  = bias[o0], b1  = bias[o0 + 8];
        float* r0 = out + ((size_t)(bidx * OUTd + o0) * Nn);
        float* r1 = out + ((size_t)(bidx * OUTd + o0 + 8) * Nn);
        #pragma unroll
        for (int nf = 0; nf < 4; nf++) {
            const int nb = nb0 + nf * 8;
            const float t0 = 16384.f * (float)acch[mf][nf][0] + 128.f * (float)accm[mf][nf][0];
            const float t1 = 16384.f * (float)acch[mf][nf][1] + 128.f * (float)accm[mf][nf][1];
            const float t2 = 16384.f * (float)acch[mf][nf][2] + 128.f * (float)accm[mf][nf][2];
            const float t3 = 16384.f * (float)acch[mf][nf][3] + 128.f * (float)accm[mf][nf][3];
            float2 w0, w1;
            w0.x = fmaxf(fmaf(t0, sa0 * sbv[nf][0], b0), 0.f);
            w0.y = fmaxf(fmaf(t1, sa0 * sbv[nf][1], b0), 0.f);
            w1.x = fmaxf(fmaf(t2, sa1 * sbv[nf][0], b1), 0.f);
            w1.y = fmaxf(fmaf(t3, sa1 * sbv[nf][1], b1), 0.f);
            *(float2*)(r0 + nb) = w0;
            *(float2*)(r1 + nb) = w1;
        }
    }
}

// ============================================================
// launch
// ============================================================
extern "C" void kernel_launch(void* const* d_in, const int* in_sizes, int n_in,
                              void* d_out, int out_size) {
    const float* x    = (const float*)d_in[0];
    const int*   edge = (const int*)d_in[1];
    const float* a_w  = (const float*)d_in[2];
    const float* a_b  = (const float*)d_in[3];
    const float* nn_w = (const float*)d_in[4];
    const float* nn_b = (const float*)d_in[5];
    float*       out  = (float*)d_out;

    k_wq       <<<OUTd, 32>>>(nn_w, edge);
    k_transpose<<<dim3(Nn / 32, Cc / 32, Bb), dim3(32, 8)>>>(x);
    k_scores   <<<(BN_TOT * 32) / 256, 256>>>(a_w);
    k_agg      <<<BN_TOT / 4, 256>>>(edge, a_b);
    k_gemm_i8  <<<dim3(NT2, MTILES), 256>>>(nn_b, out);
}

// round 13
// speedup vs baseline: 2.6121x; 1.0746x over previous
#include <cuda_runtime.h>
#include <cuda_fp16.h>
#include <cstdint>

// Problem constants
#define Bb   8
#define Cc   256
#define Nn   2048
#define Kk   16
#define OUTd 256
#define KD   512                 // 2*C
#define BN_TOT (Bb*Nn)           // 16384
#define NT2  256                 // N tiles of 64
#define MTILES 2                 // 256/128

// ---- scratch (static device globals; no dynamic allocation) ----
__device__ __half g_xsH[BN_TOT * Cc];   // fp16 node-major features
__device__ float g_si [BN_TOT];
__device__ float g_sj [BN_TOT];
__device__ int   g_is64;

// int8 split operands (Q = qh*128 + ql, |Q| <= 16256), row-major [rows][512]
__device__ signed char g_FQh[(size_t)BN_TOT * KD];
__device__ signed char g_FQl[(size_t)BN_TOT * KD];
__device__ signed char g_WQh[(size_t)OUTd * KD];
__device__ signed char g_WQl[(size_t)OUTd * KD];
__device__ float g_sf[BN_TOT];          // per-feature-row scale
__device__ float g_sa[OUTd];            // per-weight-row scale

// ============================================================
// helpers
// ============================================================
__device__ __forceinline__ uint32_t smem_u32(const void* p) {
    uint32_t a;
    asm("{ .reg .u64 t; cvta.to.shared.u64 t, %1; cvt.u32.u64 %0, t; }"
        : "=r"(a) : "l"(p));
    return a;
}
__device__ __forceinline__ void ldm4(uint32_t* r, uint32_t addr) {
    asm volatile("ldmatrix.sync.aligned.m8n8.x4.shared.b16 {%0,%1,%2,%3}, [%4];"
                 : "=r"(r[0]), "=r"(r[1]), "=r"(r[2]), "=r"(r[3]) : "r"(addr));
}
__device__ __forceinline__ void imma(int* d, const uint32_t* a, const uint32_t* b) {
    asm volatile(
        "mma.sync.aligned.m16n8k32.row.col.s32.s8.s8.s32 "
        "{%0,%1,%2,%3}, {%4,%5,%6,%7}, {%8,%9}, {%0,%1,%2,%3};"
        : "+r"(d[0]), "+r"(d[1]), "+r"(d[2]), "+r"(d[3])
        : "r"(a[0]), "r"(a[1]), "r"(a[2]), "r"(a[3]), "r"(b[0]), "r"(b[1]));
}
#define CP16(dst, src) asm volatile("cp.async.cg.shared.global [%0], [%1], 16;" :: "r"(dst), "l"(src))
#define CP_COMMIT()    asm volatile("cp.async.commit_group;" ::: "memory")
#define CP_WAIT1()     asm volatile("cp.async.wait_group 1;" ::: "memory")
#define CP_WAIT0()     asm volatile("cp.async.wait_group 0;" ::: "memory")

__device__ __forceinline__ void quant2(float v, float inv, signed char& qh,
                                       signed char& ql) {
    int Q = __float2int_rn(v * inv);         // |Q| <= 16256
    int h = (Q + 64) >> 7;                   // round(Q/128)
    qh = (signed char)h;
    ql = (signed char)(Q - (h << 7));        // in [-64,64]
}

// ============================================================
// K0: weight int8 hi/lo quantization (one block = one row) +
//     edge-dtype detection in block 0.
// ============================================================
__global__ void k_wq(const float* __restrict__ W, const int* __restrict__ e) {
    const int lane = threadIdx.x;            // 32 threads
    if (blockIdx.x == 0) {
        int bad = 0;
        #pragma unroll
        for (int i = lane; i < 256; i += 32) bad |= e[2 * i + 1];
        #pragma unroll
        for (int o = 16; o; o >>= 1) bad |= __shfl_xor_sync(0xffffffffu, bad, o);
        if (!lane) g_is64 = (bad == 0) ? 1 : 0;
    }
    const int row = blockIdx.x;
    const float* wp = W + (size_t)row * KD + lane * 16;
    float vals[16];
    float mx = 0.f;
    #pragma unroll
    for (int j = 0; j < 16; j++) { vals[j] = wp[j]; mx = fmaxf(mx, fabsf(vals[j])); }
    #pragma unroll
    for (int o = 16; o; o >>= 1) mx = fmaxf(mx, __shfl_xor_sync(0xffffffffu, mx, o));
    const float M   = fmaxf(mx, 1e-20f);
    const float inv = 16256.f / M;
    union { uint4 u; signed char c[16]; } H, L;
    #pragma unroll
    for (int j = 0; j < 16; j++) quant2(vals[j], inv, H.c[j], L.c[j]);
    const size_t o = (size_t)row * KD + lane * 16;
    *(uint4*)(g_WQh + o) = H.u;
    *(uint4*)(g_WQl + o) = L.u;
    if (!lane) g_sa[row] = M * (1.f / 16256.f);
}

// ============================================================
// K1: FUSED transpose + attention pre-scores.
//     One block owns a 32-node slab over ALL 256 channels
//     (8 c-tile iterations). Score partials accumulate in
//     registers during the load phase; 8-way smem reduce.
// ============================================================
__global__ __launch_bounds__(256) void k_transpose(const float* __restrict__ x,
                                                   const float* __restrict__ aw) {
    __shared__ float tile[32][33];
    __shared__ float sred[8][32][2];
    const int b   = blockIdx.y;
    const int n0  = blockIdx.x * 32;
    const int tx  = threadIdx.x;             // 0..31
    const int ty  = threadIdx.y;             // 0..7
    const int tid = ty * 32 + tx;
    const float* xb = x + (size_t)b * Cc * Nn;
    __half* xt = g_xsH + (size_t)b * Nn * Cc;

    float ai = 0.f, aj = 0.f;                // score partials for node n0+tx
    #pragma unroll 1
    for (int c0 = 0; c0 < Cc; c0 += 32) {
        __syncthreads();                     // tile reuse guard
        #pragma unroll
        for (int i = 0; i < 32; i += 8) {
            const int c = c0 + ty + i;
            const float v = xb[(size_t)c * Nn + n0 + tx];
            tile[ty + i][tx] = v;
            ai += v * __ldg(aw + c);
            aj += v * __ldg(aw + Cc + c);
        }
        __syncthreads();
        #pragma unroll
        for (int i = 0; i < 32; i += 8)
            xt[(size_t)(n0 + ty + i) * Cc + c0 + tx] =
                __float2half_rn(tile[tx][ty + i]);
    }
    sred[ty][tx][0] = ai;
    sred[ty][tx][1] = aj;
    __syncthreads();
    if (tid < 64) {
        const int node  = tid & 31;
        const int which = tid >> 5;
        float s = 0.f;
        #pragma unroll
        for (int r = 0; r < 8; r++) s += sred[r][node][which];
        if (which) g_sj[b * Nn + n0 + node] = s;
        else       g_si[b * Nn + n0 + node] = s;
    }
}

// ============================================================
// K4: warp-per-node FUSED softmax + aggregation + int8 quant.
//     8 nodes/block (8 warps). No smem, no __syncthreads.
// ============================================================
__global__ __launch_bounds__(256) void k_agg(const int* __restrict__ edge,
                                             const float* __restrict__ ab) {
    const int warp = threadIdx.x >> 5;
    const int lane = threadIdx.x & 31;
    const int bn   = blockIdx.x * 8 + warp;
    const int b    = bn >> 11;

    // --- softmax: lanes 0..15 and 16..31 compute identical halves ---
    const int sh  = g_is64;
    const int k16 = lane & 15;
    const size_t ei = (size_t)(bn * Kk + k16) << sh;
    const int i0 = edge[ei] & (Nn - 1);
    const int i1 = edge[(((size_t)BN_TOT * Kk) << sh) + ei] & (Nn - 1);
    const float e = g_si[b * Nn + i1] + g_sj[b * Nn + i0] + ab[0];
    float m = e;
    #pragma unroll
    for (int o = 8; o; o >>= 1) m = fmaxf(m, __shfl_xor_sync(0xffffffffu, m, o));
    const float ev = expf(e - m);
    float s = ev;
    #pragma unroll
    for (int o = 8; o; o >>= 1) s += __shfl_xor_sync(0xffffffffu, s, o);
    const float w  = ev / s;
    const int joff = i0 * 32;                // row offset in uint4 units (256 halfs)

    // --- aggregation: uint4 gathers (8 halfs/lane), fp32 accum ---
    const uint4* base4 = (const uint4*)(g_xsH + (size_t)b * Nn * Cc);
    const uint4 craw = base4[(bn & (Nn - 1)) * 32 + lane];   // center, 8 halfs
    float a0 = 0.f, a1 = 0.f, a2 = 0.f, a3 = 0.f;
    float a4 = 0.f, a5 = 0.f, a6 = 0.f, a7 = 0.f;
    #pragma unroll
    for (int k = 0; k < Kk; k++) {
        const float wk = __shfl_sync(0xffffffffu, w, k);
        const int   jo = __shfl_sync(0xffffffffu, joff, k);
        const uint4 raw = base4[jo + lane];
        const float2 p0 = __half22float2(*(const __half2*)&raw.x);
        const float2 p1 = __half22float2(*(const __half2*)&raw.y);
        const float2 p2 = __half22float2(*(const __half2*)&raw.z);
        const float2 p3 = __half22float2(*(const __half2*)&raw.w);
        a0 += wk * p0.x; a1 += wk * p0.y; a2 += wk * p1.x; a3 += wk * p1.y;
        a4 += wk * p2.x; a5 += wk * p2.y; a6 += wk * p3.x; a7 += wk * p3.y;
    }
    const float2 c0 = __half22float2(*(const __half2*)&craw.x);
    const float2 c1 = __half22float2(*(const __half2*)&craw.y);
    const float2 c2 = __half22float2(*(const __half2*)&craw.z);
    const float2 c3 = __half22float2(*(const __half2*)&craw.w);
    // interleaved feat values: 16 per lane (channels 8*lane..8*lane+7)
    const float v[16] = {c0.x, a0, c0.y, a1, c1.x, a2, c1.y, a3,
                         c2.x, a4, c2.y, a5, c3.x, a6, c3.y, a7};

    // --- full-row max (512 entries across 32 lanes) ---
    float mx = 0.f;
    #pragma unroll
    for (int j = 0; j < 16; j++) mx = fmaxf(mx, fabsf(v[j]));
    #pragma unroll
    for (int o = 16; o; o >>= 1) mx = fmaxf(mx, __shfl_xor_sync(0xffffffffu, mx, o));
    const float M   = fmaxf(mx, 1e-20f);
    const float inv = 16256.f / M;
    union { uint4 u; signed char ch[16]; } H, L;
    #pragma unroll
    for (int j = 0; j < 16; j++) quant2(v[j], inv, H.ch[j], L.ch[j]);
    const size_t o = (size_t)bn * KD + 16 * lane;
    *(uint4*)(g_FQh + o) = H.u;
    *(uint4*)(g_FQl + o) = L.u;
    if (!lane) g_sf[bn] = M * (1.f / 16256.f);
}

// ============================================================
// K5: int8-split GEMM, CTA 128(M)x64(N), 2 CTAs/SM.
//     8 warps, 32x32 warp tiles. cp.async double-buffered.
//     smem rows: [0,128) WH | [128,256) WL | [256,320) FH | [320,384) FL
// ============================================================
#define PITCH8 48
#define SROWS  384
#define BUFB   (SROWS * PITCH8)   // 18432 bytes

__global__ __launch_bounds__(256, 2)
void k_gemm_i8(const float* __restrict__ bias, float* __restrict__ out) {
    __shared__ __align__(16) signed char sm[2][SROWS][PITCH8];

    const int tid  = threadIdx.x;
    const int lane = tid & 31;
    const int warp = tid >> 5;
    const int wm   = warp >> 1;     // 0..3  (m offset wm*32)
    const int wn   = warp & 1;      // 0..1  (n offset wn*32)
    const int nt   = blockIdx.x;    // 0..255 (64-col tiles)
    const int mt   = blockIdx.y;    // 0..1

    const int lrow  = tid >> 1;
    const int lhalf = tid & 1;
    const signed char* pWH = g_WQh + (size_t)(mt * 128 + lrow) * KD + lhalf * 16;
    const signed char* pWL = g_WQl + (size_t)(mt * 128 + lrow) * KD + lhalf * 16;
    const signed char* pFH = g_FQh + (size_t)(nt * 64 + (lrow & 63)) * KD + lhalf * 16;
    const signed char* pFL = g_FQl + (size_t)(nt * 64 + (lrow & 63)) * KD + lhalf * 16;
    const uint32_t dWH = smem_u32(&sm[0][lrow][lhalf * 16]);
    const uint32_t dWL = smem_u32(&sm[0][128 + lrow][lhalf * 16]);
    const uint32_t dFH = smem_u32(&sm[0][256 + (lrow & 63)][lhalf * 16]);
    const uint32_t dFL = smem_u32(&sm[0][320 + (lrow & 63)][lhalf * 16]);
    const bool doF = (tid < 128);

    #pragma unroll
    for (int s = 0; s < 2; s++) {
        const int ko = s * 32;
        const uint32_t bo = s * BUFB;
        CP16(dWH + bo, pWH + ko);
        CP16(dWL + bo, pWL + ko);
        if (doF) { CP16(dFH + bo, pFH + ko); CP16(dFL + bo, pFL + ko); }
        CP_COMMIT();
    }

    int acch[2][4][4], accm[2][4][4];
    #pragma unroll
    for (int i = 0; i < 2; i++)
        #pragma unroll
        for (int j = 0; j < 4; j++)
            #pragma unroll
            for (int q = 0; q < 4; q++) { acch[i][j][q] = 0; accm[i][j][q] = 0; }

    const int arow = wm * 32 + (lane & 7) + ((lane >> 3) & 1) * 8;   // + mf*16
    const int akb  = ((lane >> 4) & 1) * 16;
    const int brow = wn * 32 + ((lane >> 4) & 1) * 8 + (lane & 7);   // + p*16
    const int bkb  = ((lane >> 3) & 1) * 16;

    #pragma unroll 1
    for (int kt = 0; kt < KD / 32; kt++) {
        const int buf = kt & 1;
        if (kt < KD / 32 - 1) CP_WAIT1(); else CP_WAIT0();
        __syncthreads();

        uint32_t bqh[4][2], bql[4][2];
        #pragma unroll
        for (int p = 0; p < 2; p++) {
            uint32_t r[4];
            ldm4(r, smem_u32(&sm[buf][256 + brow + p * 16][bkb]));
            bqh[2 * p][0] = r[0]; bqh[2 * p][1] = r[1];
            bqh[2 * p + 1][0] = r[2]; bqh[2 * p + 1][1] = r[3];
            ldm4(r, smem_u32(&sm[buf][320 + brow + p * 16][bkb]));
            bql[2 * p][0] = r[0]; bql[2 * p][1] = r[1];
            bql[2 * p + 1][0] = r[2]; bql[2 * p + 1][1] = r[3];
        }
        #pragma unroll
        for (int mf = 0; mf < 2; mf++) {
            uint32_t ah[4], al[4];
            ldm4(ah, smem_u32(&sm[buf][arow + mf * 16][akb]));
            ldm4(al, smem_u32(&sm[buf][128 + arow + mf * 16][akb]));
            #pragma unroll
            for (int nf = 0; nf < 4; nf++) {
                imma(acch[mf][nf], ah, bqh[nf]);   // hh
                imma(accm[mf][nf], ah, bql[nf]);   // hl
                imma(accm[mf][nf], al, bqh[nf]);   // lh
            }
        }
        __syncthreads();
        if (kt + 2 < KD / 32) {
            const int ko = (kt + 2) * 32;
            const uint32_t bo = buf * BUFB;
            CP16(dWH + bo, pWH + ko);
            CP16(dWL + bo, pWL + ko);
            if (doF) { CP16(dFH + bo, pFH + ko); CP16(dFL + bo, pFL + ko); }
            CP_COMMIT();
        }
    }

    // epilogue: scale-combine + bias + relu
    const int g    = lane >> 2;
    const int tig  = lane & 3;
    const int bidx = nt >> 5;                  // 32 tiles per batch
    float sbv[4][2];
    #pragma unroll
    for (int nf = 0; nf < 4; nf++) {
        const int col = nt * 64 + wn * 32 + 2 * tig + nf * 8;
        sbv[nf][0] = g_sf[col];
        sbv[nf][1] = g_sf[col + 1];
    }
    const int nb0 = (nt & 31) * 64 + wn * 32 + 2 * tig;
    #pragma unroll
    for (int mf = 0; mf < 2; mf++) {
        const int o0 = mt * 128 + wm * 32 + mf * 16 + g;
        const float sa0 = g_sa[o0], sa1 = g_sa[o0 + 8];
        const float b0  = bias[o0], b1  = bias[o0 + 8];
        float* r0 = out + ((size_t)(bidx * OUTd + o0) * Nn);
        float* r1 = out + ((size_t)(bidx * OUTd + o0 + 8) * Nn);
        #pragma unroll
        for (int nf = 0; nf < 4; nf++) {
            const int nb = nb0 + nf * 8;
            const float t0 = 16384.f * (float)acch[mf][nf][0] + 128.f * (float)accm[mf][nf][0];
            const float t1 = 16384.f * (float)acch[mf][nf][1] + 128.f * (float)accm[mf][nf][1];
            const float t2 = 16384.f * (float)acch[mf][nf][2] + 128.f * (float)accm[mf][nf][2];
            const float t3 = 16384.f * (float)acch[mf][nf][3] + 128.f * (float)accm[mf][nf][3];
            float2 w0, w1;
            w0.x = fmaxf(fmaf(t0, sa0 * sbv[nf][0], b0), 0.f);
            w0.y = fmaxf(fmaf(t1, sa0 * sbv[nf][1], b0), 0.f);
            w1.x = fmaxf(fmaf(t2, sa1 * sbv[nf][0], b1), 0.f);
            w1.y = fmaxf(fmaf(t3, sa1 * sbv[nf][1], b1), 0.f);
            *(float2*)(r0 + nb) = w0;
            *(float2*)(r1 + nb) = w1;
        }
    }
}

// ============================================================
// launch
// ============================================================
extern "C" void kernel_launch(void* const* d_in, const int* in_sizes, int n_in,
                              void* d_out, int out_size) {
    const float* x    = (const float*)d_in[0];
    const int*   edge = (const int*)d_in[1];
    const float* a_w  = (const float*)d_in[2];
    const float* a_b  = (const float*)d_in[3];
    const float* nn_w = (const float*)d_in[4];
    const float* nn_b = (const float*)d_in[5];
    float*       out  = (float*)d_out;

    k_wq       <<<OUTd, 32>>>(nn_w, edge);
    k_transpose<<<dim3(Nn / 32, Bb), dim3(32, 8)>>>(x, a_w);
    k_agg      <<<BN_TOT / 8, 256>>>(edge, a_b);
    k_gemm_i8  <<<dim3(NT2, MTILES), 256>>>(nn_b, out);
}

// round 15
// speedup vs baseline: 2.9494x; 1.1291x over previous
#include <cuda_runtime.h>
#include <cuda_fp16.h>
#include <cstdint>

// Problem constants
#define Bb   8
#define Cc   256
#define Nn   2048
#define Kk   16
#define OUTd 256
#define KD   512                 // 2*C
#define BN_TOT (Bb*Nn)           // 16384
#define NT2  256                 // N tiles of 64
#define MTILES 2                 // 256/128

// ---- scratch (static device globals; no dynamic allocation) ----
__device__ __half g_xsH[BN_TOT * Cc];   // fp16 node-major features
__device__ float g_si [BN_TOT];
__device__ float g_sj [BN_TOT];
__device__ int   g_is64;

// int8 split operands (Q = qh*128 + ql, |Q| <= 16256), row-major [rows][512]
__device__ signed char g_FQh[(size_t)BN_TOT * KD];
__device__ signed char g_FQl[(size_t)BN_TOT * KD];
__device__ signed char g_WQh[(size_t)OUTd * KD];
__device__ signed char g_WQl[(size_t)OUTd * KD];
__device__ float g_sf[BN_TOT];          // per-feature-row scale
__device__ float g_sa[OUTd];            // per-weight-row scale

// ============================================================
// helpers
// ============================================================
__device__ __forceinline__ uint32_t smem_u32(const void* p) {
    uint32_t a;
    asm("{ .reg .u64 t; cvta.to.shared.u64 t, %1; cvt.u32.u64 %0, t; }"
        : "=r"(a) : "l"(p));
    return a;
}
__device__ __forceinline__ void ldm4(uint32_t* r, uint32_t addr) {
    asm volatile("ldmatrix.sync.aligned.m8n8.x4.shared.b16 {%0,%1,%2,%3}, [%4];"
                 : "=r"(r[0]), "=r"(r[1]), "=r"(r[2]), "=r"(r[3]) : "r"(addr));
}
__device__ __forceinline__ void imma(int* d, const uint32_t* a, const uint32_t* b) {
    asm volatile(
        "mma.sync.aligned.m16n8k32.row.col.s32.s8.s8.s32 "
        "{%0,%1,%2,%3}, {%4,%5,%6,%7}, {%8,%9}, {%0,%1,%2,%3};"
        : "+r"(d[0]), "+r"(d[1]), "+r"(d[2]), "+r"(d[3])
        : "r"(a[0]), "r"(a[1]), "r"(a[2]), "r"(a[3]), "r"(b[0]), "r"(b[1]));
}
#define CP16(dst, src) asm volatile("cp.async.cg.shared.global [%0], [%1], 16;" :: "r"(dst), "l"(src))
#define CP_COMMIT()    asm volatile("cp.async.commit_group;" ::: "memory")
#define CP_WAIT1()     asm volatile("cp.async.wait_group 1;" ::: "memory")
#define CP_WAIT0()     asm volatile("cp.async.wait_group 0;" ::: "memory")

__device__ __forceinline__ void quant2(float v, float inv, signed char& qh,
                                       signed char& ql) {
    int Q = __float2int_rn(v * inv);         // |Q| <= 16256
    int h = (Q + 64) >> 7;                   // round(Q/128)
    qh = (signed char)h;
    ql = (signed char)(Q - (h << 7));        // in [-64,64]
}

// swizzled byte offset of 16B chunk c in row r (pitch 64):
//   r*64 + (c ^ ((r>>1)&3))*16  -> ldmatrix conflict-free for
//   8-row groups starting at r % 8 == 0, any fixed c.
__device__ __forceinline__ uint32_t sws(int r, int c) {
    return (uint32_t)(r * 64 + ((c ^ ((r >> 1) & 3)) << 4));
}

// ============================================================
// K0: weight int8 hi/lo quantization (one block = one row) +
//     edge-dtype detection in block 0.
// ============================================================
__global__ void k_wq(const float* __restrict__ W, const int* __restrict__ e) {
    const int lane = threadIdx.x;            // 32 threads
    if (blockIdx.x == 0) {
        int bad = 0;
        #pragma unroll
        for (int i = lane; i < 256; i += 32) bad |= e[2 * i + 1];
        #pragma unroll
        for (int o = 16; o; o >>= 1) bad |= __shfl_xor_sync(0xffffffffu, bad, o);
        if (!lane) g_is64 = (bad == 0) ? 1 : 0;
    }
    const int row = blockIdx.x;
    const float* wp = W + (size_t)row * KD + lane * 16;
    float vals[16];
    float mx = 0.f;
    #pragma unroll
    for (int j = 0; j < 16; j++) { vals[j] = wp[j]; mx = fmaxf(mx, fabsf(vals[j])); }
    #pragma unroll
    for (int o = 16; o; o >>= 1) mx = fmaxf(mx, __shfl_xor_sync(0xffffffffu, mx, o));
    const float M   = fmaxf(mx, 1e-20f);
    const float inv = 16256.f / M;
    union { uint4 u; signed char c[16]; } H, L;
    #pragma unroll
    for (int j = 0; j < 16; j++) quant2(vals[j], inv, H.c[j], L.c[j]);
    const size_t o = (size_t)row * KD + lane * 16;
    *(uint4*)(g_WQh + o) = H.u;
    *(uint4*)(g_WQl + o) = L.u;
    if (!lane) g_sa[row] = M * (1.f / 16256.f);
}

// ============================================================
// K1: FUSED transpose + attention pre-scores.
// ============================================================
__global__ __launch_bounds__(256) void k_transpose(const float* __restrict__ x,
                                                   const float* __restrict__ aw) {
    __shared__ float tile[32][33];
    __shared__ float sred[8][32][2];
    const int b   = blockIdx.y;
    const int n0  = blockIdx.x * 32;
    const int tx  = threadIdx.x;             // 0..31
    const int ty  = threadIdx.y;             // 0..7
    const int tid = ty * 32 + tx;
    const float* xb = x + (size_t)b * Cc * Nn;
    __half* xt = g_xsH + (size_t)b * Nn * Cc;

    float ai = 0.f, aj = 0.f;                // score partials for node n0+tx
    #pragma unroll 1
    for (int c0 = 0; c0 < Cc; c0 += 32) {
        __syncthreads();                     // tile reuse guard
        #pragma unroll
        for (int i = 0; i < 32; i += 8) {
            const int c = c0 + ty + i;
            const float v = xb[(size_t)c * Nn + n0 + tx];
            tile[ty + i][tx] = v;
            ai += v * __ldg(aw + c);
            aj += v * __ldg(aw + Cc + c);
        }
        __syncthreads();
        #pragma unroll
        for (int i = 0; i < 32; i += 8)
            xt[(size_t)(n0 + ty + i) * Cc + c0 + tx] =
                __float2half_rn(tile[tx][ty + i]);
    }
    sred[ty][tx][0] = ai;
    sred[ty][tx][1] = aj;
    __syncthreads();
    if (tid < 64) {
        const int node  = tid & 31;
        const int which = tid >> 5;
        float s = 0.f;
        #pragma unroll
        for (int r = 0; r < 8; r++) s += sred[r][node][which];
        if (which) g_sj[b * Nn + n0 + node] = s;
        else       g_si[b * Nn + n0 + node] = s;
    }
}

// ============================================================
// K4: warp-per-node FUSED softmax + aggregation + int8 quant.
// ============================================================
__global__ __launch_bounds__(256) void k_agg(const int* __restrict__ edge,
                                             const float* __restrict__ ab) {
    const int warp = threadIdx.x >> 5;
    const int lane = threadIdx.x & 31;
    const int bn   = blockIdx.x * 8 + warp;
    const int b    = bn >> 11;

    // --- softmax: lanes 0..15 and 16..31 compute identical halves ---
    const int sh  = g_is64;
    const int k16 = lane & 15;
    const size_t ei = (size_t)(bn * Kk + k16) << sh;
    const int i0 = edge[ei] & (Nn - 1);
    const int i1 = edge[(((size_t)BN_TOT * Kk) << sh) + ei] & (Nn - 1);
    const float e = g_si[b * Nn + i1] + g_sj[b * Nn + i0] + ab[0];
    float m = e;
    #pragma unroll
    for (int o = 8; o; o >>= 1) m = fmaxf(m, __shfl_xor_sync(0xffffffffu, m, o));
    const float ev = expf(e - m);
    float s = ev;
    #pragma unroll
    for (int o = 8; o; o >>= 1) s += __shfl_xor_sync(0xffffffffu, s, o);
    const float w  = ev / s;
    const int joff = i0 * 32;                // row offset in uint4 units

    // --- aggregation: uint4 gathers (8 halfs/lane), fp32 accum ---
    const uint4* base4 = (const uint4*)(g_xsH + (size_t)b * Nn * Cc);
    const uint4 craw = base4[(bn & (Nn - 1)) * 32 + lane];   // center, 8 halfs
    float a0 = 0.f, a1 = 0.f, a2 = 0.f, a3 = 0.f;
    float a4 = 0.f, a5 = 0.f, a6 = 0.f, a7 = 0.f;
    #pragma unroll
    for (int k = 0; k < Kk; k++) {
        const float wk = __shfl_sync(0xffffffffu, w, k);
        const int   jo = __shfl_sync(0xffffffffu, joff, k);
        const uint4 raw = base4[jo + lane];
        const float2 p0 = __half22float2(*(const __half2*)&raw.x);
        const float2 p1 = __half22float2(*(const __half2*)&raw.y);
        const float2 p2 = __half22float2(*(const __half2*)&raw.z);
        const float2 p3 = __half22float2(*(const __half2*)&raw.w);
        a0 += wk * p0.x; a1 += wk * p0.y; a2 += wk * p1.x; a3 += wk * p1.y;
        a4 += wk * p2.x; a5 += wk * p2.y; a6 += wk * p3.x; a7 += wk * p3.y;
    }
    const float2 c0 = __half22float2(*(const __half2*)&craw.x);
    const float2 c1 = __half22float2(*(const __half2*)&craw.y);
    const float2 c2 = __half22float2(*(const __half2*)&craw.z);
    const float2 c3 = __half22float2(*(const __half2*)&craw.w);
    const float v[16] = {c0.x, a0, c0.y, a1, c1.x, a2, c1.y, a3,
                         c2.x, a4, c2.y, a5, c3.x, a6, c3.y, a7};

    float mx = 0.f;
    #pragma unroll
    for (int j = 0; j < 16; j++) mx = fmaxf(mx, fabsf(v[j]));
    #pragma unroll
    for (int o = 16; o; o >>= 1) mx = fmaxf(mx, __shfl_xor_sync(0xffffffffu, mx, o));
    const float M   = fmaxf(mx, 1e-20f);
    const float inv = 16256.f / M;
    union { uint4 u; signed char ch[16]; } H, L;
    #pragma unroll
    for (int j = 0; j < 16; j++) quant2(v[j], inv, H.ch[j], L.ch[j]);
    const size_t o = (size_t)bn * KD + 16 * lane;
    *(uint4*)(g_FQh + o) = H.u;
    *(uint4*)(g_FQl + o) = L.u;
    if (!lane) g_sf[bn] = M * (1.f / 16256.f);
}

// ============================================================
// K5: int8-split GEMM, CTA 128(M)x64(N), BK=64 per stage,
//     2 CTAs/SM, 8 warps, 32x32 warp tiles, cp.async x2 buffers.
//     smem rows (pitch 64, XOR-swizzled 16B chunks):
//       [0,128) WH | [128,256) WL | [256,320) FH | [320,384) FL
//     Total 2*384*64 = 49152 B (static smem limit, exactly).
// ============================================================
#define SROWS  384
#define BUFB   (SROWS * 64)       // 24576 bytes per buffer

__global__ __launch_bounds__(256, 2)
void k_gemm_i8(const float* __restrict__ bias, float* __restrict__ out) {
    __shared__ __align__(16) signed char sm[2][SROWS][64];

    const int tid  = threadIdx.x;
    const int lane = tid & 31;
    const int warp = tid >> 5;
    const int wm   = warp >> 1;     // 0..3  (m offset wm*32)
    const int wn   = warp & 1;      // 0..1  (n offset wn*32)
    const int nt   = blockIdx.x;    // 0..255 (64-col tiles)
    const int mt   = blockIdx.y;    // 0..1
    const uint32_t smb = smem_u32(sm);

    // staging: W rows via (tid>>1, 2 chunks), F rows via (tid>>2, 1 chunk)
    const int rowW = tid >> 1;              // 0..127
    const int chW  = (tid & 1) * 2;         // chunks {0,1} or {2,3}
    const int rowF = tid >> 2;              // 0..63
    const int chF  = tid & 3;               // 0..3
    const signed char* pWH = g_WQh + (size_t)(mt * 128 + rowW) * KD + chW * 16;
    const signed char* pWL = g_WQl + (size_t)(mt * 128 + rowW) * KD + chW * 16;
    const signed char* pFH = g_FQh + (size_t)(nt * 64 + rowF) * KD + chF * 16;
    const signed char* pFL = g_FQl + (size_t)(nt * 64 + rowF) * KD + chF * 16;
    const uint32_t dWH0 = smb + sws(rowW, chW);
    const uint32_t dWH1 = smb + sws(rowW, chW + 1);
    const uint32_t dWL0 = smb + sws(128 + rowW, chW);
    const uint32_t dWL1 = smb + sws(128 + rowW, chW + 1);
    const uint32_t dFH  = smb + sws(256 + rowF, chF);
    const uint32_t dFL  = smb + sws(320 + rowF, chF);

    // prologue: stages 0 and 1 in flight (stage = 64 bytes of K)
    #pragma unroll
    for (int s = 0; s < 2; s++) {
        const int ko = s * 64;
        const uint32_t bo = s * BUFB;
        CP16(dWH0 + bo, pWH + ko);
        CP16(dWH1 + bo, pWH + ko + 16);
        CP16(dWL0 + bo, pWL + ko);
        CP16(dWL1 + bo, pWL + ko + 16);
        CP16(dFH + bo, pFH + ko);
        CP16(dFL + bo, pFL + ko);
        CP_COMMIT();
    }

    int acch[2][4][4], accm[2][4][4];
    #pragma unroll
    for (int i = 0; i < 2; i++)
        #pragma unroll
        for (int j = 0; j < 4; j++)
            #pragma unroll
            for (int q = 0; q < 4; q++) { acch[i][j][q] = 0; accm[i][j][q] = 0; }

    const int arow = wm * 32 + (lane & 7) + ((lane >> 3) & 1) * 8;   // + mf*16
    const int ach  = (lane >> 4) & 1;                                // chunk within K=32
    const int brow = wn * 32 + ((lane >> 4) & 1) * 8 + (lane & 7);   // + p*16
    const int bch  = (lane >> 3) & 1;

    #pragma unroll 1
    for (int kt = 0; kt < KD / 64; kt++) {       // 8 stages
        const int buf = kt & 1;
        if (kt < KD / 64 - 1) CP_WAIT1(); else CP_WAIT0();
        __syncthreads();
        const uint32_t sb = smb + buf * BUFB;

        #pragma unroll
        for (int ks = 0; ks < 2; ks++) {         // two K=32 sub-chunks
            const int cA = ks * 2 + ach;
            const int cB = ks * 2 + bch;
            uint32_t bqh[4][2], bql[4][2];
            #pragma unroll
            for (int p = 0; p < 2; p++) {
                uint32_t r[4];
                ldm4(r, sb + sws(256 + brow + p * 16, cB));
                bqh[2 * p][0] = r[0]; bqh[2 * p][1] = r[1];
                bqh[2 * p + 1][0] = r[2]; bqh[2 * p + 1][1] = r[3];
                ldm4(r, sb + sws(320 + brow + p * 16, cB));
                bql[2 * p][0] = r[0]; bql[2 * p][1] = r[1];
                bql[2 * p + 1][0] = r[2]; bql[2 * p + 1][1] = r[3];
            }
            #pragma unroll
            for (int mf = 0; mf < 2; mf++) {
                uint32_t ah[4], al[4];
                ldm4(ah, sb + sws(arow + mf * 16, cA));
                ldm4(al, sb + sws(128 + arow + mf * 16, cA));
                #pragma unroll
                for (int nf = 0; nf < 4; nf++) {
                    imma(acch[mf][nf], ah, bqh[nf]);   // hh
                    imma(accm[mf][nf], ah, bql[nf]);   // hl
                    imma(accm[mf][nf], al, bqh[nf]);   // lh
                }
            }
        }
        __syncthreads();
        if (kt + 2 < KD / 64) {
            const int ko = (kt + 2) * 64;
            const uint32_t bo = buf * BUFB;
            CP16(dWH0 + bo, pWH + ko);
            CP16(dWH1 + bo, pWH + ko + 16);
            CP16(dWL0 + bo, pWL + ko);
            CP16(dWL1 + bo, pWL + ko + 16);
            CP16(dFH + bo, pFH + ko);
            CP16(dFL + bo, pFL + ko);
            CP_COMMIT();
        }
    }

    // epilogue: scale-combine + bias + relu
    const int g    = lane >> 2;
    const int tig  = lane & 3;
    const int bidx = nt >> 5;                  // 32 tiles per batch
    float sbv[4][2];
    #pragma unroll
    for (int nf = 0; nf < 4; nf++) {
        const int col = nt * 64 + wn * 32 + 2 * tig + nf * 8;
        sbv[nf][0] = g_sf[col];
        sbv[nf][1] = g_sf[col + 1];
    }
    const int nb0 = (nt & 31) * 64 + wn * 32 + 2 * tig;
    #pragma unroll
    for (int mf = 0; mf < 2; mf++) {
        const int o0 = mt * 128 + wm * 32 + mf * 16 + g;
        const float sa0 = g_sa[o0], sa1 = g_sa[o0 + 8];
        const float b0  = bias[o0], b1  = bias[o0 + 8];
        float* r0 = out + ((size_t)(bidx * OUTd + o0) * Nn);
        float* r1 = out + ((size_t)(bidx * OUTd + o0 + 8) * Nn);
        #pragma unroll
        for (int nf = 0; nf < 4; nf++) {
            const int nb = nb0 + nf * 8;
            const float t0 = 16384.f * (float)acch[mf][nf][0] + 128.f * (float)accm[mf][nf][0];
            const float t1 = 16384.f * (float)acch[mf][nf][1] + 128.f * (float)accm[mf][nf][1];
            const float t2 = 16384.f * (float)acch[mf][nf][2] + 128.f * (float)accm[mf][nf][2];
            const float t3 = 16384.f * (float)acch[mf][nf][3] + 128.f * (float)accm[mf][nf][3];
            float2 w0, w1;
            w0.x = fmaxf(fmaf(t0, sa0 * sbv[nf][0], b0), 0.f);
            w0.y = fmaxf(fmaf(t1, sa0 * sbv[nf][1], b0), 0.f);
            w1.x = fmaxf(fmaf(t2, sa1 * sbv[nf][0], b1), 0.f);
            w1.y = fmaxf(fmaf(t3, sa1 * sbv[nf][1], b1), 0.f);
            *(float2*)(r0 + nb) = w0;
            *(float2*)(r1 + nb) = w1;
        }
    }
}

// ============================================================
// launch
// ============================================================
extern "C" void kernel_launch(void* const* d_in, const int* in_sizes, int n_in,
                              void* d_out, int out_size) {
    const float* x    = (const float*)d_in[0];
    const int*   edge = (const int*)d_in[1];
    const float* a_w  = (const float*)d_in[2];
    const float* a_b  = (const float*)d_in[3];
    const float* nn_w = (const float*)d_in[4];
    const float* nn_b = (const float*)d_in[5];
    float*       out  = (float*)d_out;

    k_wq       <<<OUTd, 32>>>(nn_w, edge);
    k_transpose<<<dim3(Nn / 32, Bb), dim3(32, 8)>>>(x, a_w);
    k_agg      <<<BN_TOT / 8, 256>>>(edge, a_b);
    k_gemm_i8  <<<dim3(NT2, MTILES), 256>>>(nn_b, out);
}